// round 3
// baseline (speedup 1.0000x reference)
#include <cuda_runtime.h>
#include <math.h>

// Shapes (fixed by problem)
// B=8, L=64, S=2048, D=1024, C=1024, H=16, HD=64

// ---------------- device scratch ----------------
__device__ float g_Wqh[1024 * 1024];
__device__ float g_Wkh[1024 * 1024];
__device__ float g_Wvh[1024 * 1024];
__device__ float g_bqh[1024];
__device__ float g_bkh[1024];
__device__ float g_bvh[1024];
__device__ float g_qh[512 * 1024];      // also reused for attn_out
__device__ float g_kh[16384 * 1024];
__device__ float g_vh[16384 * 1024];
__device__ float g_probs[8192 * 2048];  // [B,H,L,S]
__device__ float g_attn[512 * 1024];    // attn concat; reused for ff2 out
__device__ float g_x[512 * 1024];       // post-LN1
__device__ float g_h1[512 * 4096];      // ff hidden

__device__ __forceinline__ float gelu_exact(float x) {
    return 0.5f * x * (1.0f + erff(x * 0.70710678118654752f));
}

// ---------------- bias fusion: bout[o] = sum_i W[o,i]*bin[i] + badd[o] ----------------
__global__ void fuse_bias_kernel(const float* __restrict__ W, const float* __restrict__ bin,
                                 const float* __restrict__ badd, float* __restrict__ bout) {
    int o = blockIdx.x;
    float s = 0.f;
    for (int i = threadIdx.x; i < 1024; i += 256) s += W[o * 1024 + i] * bin[i];
    __shared__ float red[256];
    red[threadIdx.x] = s;
    __syncthreads();
    for (int st = 128; st > 0; st >>= 1) {
        if (threadIdx.x < st) red[threadIdx.x] += red[threadIdx.x + st];
        __syncthreads();
    }
    if (threadIdx.x == 0) bout[o] = red[0] + badd[o];
}

// ---------------- NN GEMM 1024x1024x1024: C = A @ B (all row-major) ----------------
__global__ void gemm_nn_1024(const float* __restrict__ A, const float* __restrict__ B,
                             float* __restrict__ C) {
    const int K = 1024, N = 1024;
    __shared__ float As[16][132];
    __shared__ float Bs[16][132];
    int tid = threadIdx.x;
    int bm = blockIdx.y * 128, bn = blockIdx.x * 128;
    int tx = tid & 15, ty = tid >> 4;
    float acc[8][8] = {};
    for (int k0 = 0; k0 < K; k0 += 16) {
#pragma unroll
        for (int it = 0; it < 2; ++it) {
            int v = tid + it * 256;
            int r = v >> 2, kv = (v & 3) * 4;
            float4 a = *(const float4*)(A + (size_t)(bm + r) * K + k0 + kv);
            As[kv + 0][r] = a.x; As[kv + 1][r] = a.y; As[kv + 2][r] = a.z; As[kv + 3][r] = a.w;
            int kk = v >> 5, c = (v & 31) * 4;
            *(float4*)&Bs[kk][c] = *(const float4*)(B + (size_t)(k0 + kk) * N + bn + c);
        }
        __syncthreads();
#pragma unroll
        for (int kk = 0; kk < 16; ++kk) {
            float a[8], bb[8];
            *(float4*)a = *(const float4*)&As[kk][ty * 8];
            *(float4*)(a + 4) = *(const float4*)&As[kk][ty * 8 + 4];
            *(float4*)bb = *(const float4*)&Bs[kk][tx * 8];
            *(float4*)(bb + 4) = *(const float4*)&Bs[kk][tx * 8 + 4];
#pragma unroll
            for (int i = 0; i < 8; ++i)
#pragma unroll
                for (int j = 0; j < 8; ++j) acc[i][j] += a[i] * bb[j];
        }
        __syncthreads();
    }
#pragma unroll
    for (int i = 0; i < 8; ++i) {
        int row = bm + ty * 8 + i;
#pragma unroll
        for (int j = 0; j < 8; j += 4) {
            float4 o;
            o.x = acc[i][j]; o.y = acc[i][j + 1]; o.z = acc[i][j + 2]; o.w = acc[i][j + 3];
            *(float4*)(C + (size_t)row * N + bn + tx * 8 + j) = o;
        }
    }
}

// ---------------- NT GEMM: C[M,N] = A[M,K] @ B[N,K]^T + bias[N]  (EPI=1 adds exact GELU) --
template <int EPI>
__global__ void gemm_nt(const float* __restrict__ A, const float* __restrict__ B,
                        const float* __restrict__ bias, float* __restrict__ C,
                        int M, int N, int K) {
    __shared__ float As[16][132];
    __shared__ float Bs[16][132];
    int tid = threadIdx.x;
    int bm = blockIdx.y * 128, bn = blockIdx.x * 128;
    int tx = tid & 15, ty = tid >> 4;
    float acc[8][8] = {};
    const float* Ab = A + (size_t)bm * K;
    const float* Bb = B + (size_t)bn * K;
    for (int k0 = 0; k0 < K; k0 += 16) {
#pragma unroll
        for (int it = 0; it < 2; ++it) {
            int v = tid + it * 256;
            int r = v >> 2, kv = (v & 3) * 4;
            float4 a = *(const float4*)(Ab + (size_t)r * K + k0 + kv);
            As[kv + 0][r] = a.x; As[kv + 1][r] = a.y; As[kv + 2][r] = a.z; As[kv + 3][r] = a.w;
            float4 b = *(const float4*)(Bb + (size_t)r * K + k0 + kv);
            Bs[kv + 0][r] = b.x; Bs[kv + 1][r] = b.y; Bs[kv + 2][r] = b.z; Bs[kv + 3][r] = b.w;
        }
        __syncthreads();
#pragma unroll
        for (int kk = 0; kk < 16; ++kk) {
            float a[8], bb[8];
            *(float4*)a = *(const float4*)&As[kk][ty * 8];
            *(float4*)(a + 4) = *(const float4*)&As[kk][ty * 8 + 4];
            *(float4*)bb = *(const float4*)&Bs[kk][tx * 8];
            *(float4*)(bb + 4) = *(const float4*)&Bs[kk][tx * 8 + 4];
#pragma unroll
            for (int i = 0; i < 8; ++i)
#pragma unroll
                for (int j = 0; j < 8; ++j) acc[i][j] += a[i] * bb[j];
        }
        __syncthreads();
    }
#pragma unroll
    for (int i = 0; i < 8; ++i) {
        int row = bm + ty * 8 + i;
#pragma unroll
        for (int j = 0; j < 8; j += 4) {
            int col = bn + tx * 8 + j;
            float4 o;
            o.x = acc[i][j] + bias[col];
            o.y = acc[i][j + 1] + bias[col + 1];
            o.z = acc[i][j + 2] + bias[col + 2];
            o.w = acc[i][j + 3] + bias[col + 3];
            if (EPI == 1) {
                o.x = gelu_exact(o.x); o.y = gelu_exact(o.y);
                o.z = gelu_exact(o.z); o.w = gelu_exact(o.w);
            }
            *(float4*)(C + (size_t)row * N + col) = o;
        }
    }
}

// ---------------- scores: per (b,h), chunk of 64 s; scores = Q K^T / 8, masked ----------
__global__ void scores_kernel(const float* __restrict__ qh, const float* __restrict__ kh,
                              const int* __restrict__ cmask, float* __restrict__ probs) {
    int bh = blockIdx.y;
    int b = bh >> 4, h = bh & 15;
    int s0 = blockIdx.x * 64;
    __shared__ float Qs[64][64];  // [k][l]
    __shared__ float Ks[64][68];  // [k][s_local]
    int tid = threadIdx.x;
#pragma unroll
    for (int it = 0; it < 4; ++it) {
        int v = tid + it * 256;
        int r = v >> 4, kv = (v & 15) * 4;
        float4 q = *(const float4*)(qh + (size_t)(b * 64 + r) * 1024 + h * 64 + kv);
        Qs[kv + 0][r] = q.x; Qs[kv + 1][r] = q.y; Qs[kv + 2][r] = q.z; Qs[kv + 3][r] = q.w;
        float4 k = *(const float4*)(kh + (size_t)(b * 2048 + s0 + r) * 1024 + h * 64 + kv);
        Ks[kv + 0][r] = k.x; Ks[kv + 1][r] = k.y; Ks[kv + 2][r] = k.z; Ks[kv + 3][r] = k.w;
    }
    __syncthreads();
    int tx = tid & 15, ty = tid >> 4;
    float acc[4][4] = {};
#pragma unroll 8
    for (int k = 0; k < 64; ++k) {
        float a[4], bb[4];
        *(float4*)a = *(const float4*)&Qs[k][ty * 4];
        *(float4*)bb = *(const float4*)&Ks[k][tx * 4];
#pragma unroll
        for (int i = 0; i < 4; ++i)
#pragma unroll
            for (int j = 0; j < 4; ++j) acc[i][j] += a[i] * bb[j];
    }
    const float NEG = __int_as_float(0xff800000);  // -inf
    int m[4];
#pragma unroll
    for (int j = 0; j < 4; ++j) m[j] = cmask[b * 2048 + s0 + tx * 4 + j];
#pragma unroll
    for (int i = 0; i < 4; ++i) {
        int l = ty * 4 + i;
        float4 o;
        o.x = m[0] ? acc[i][0] * 0.125f : NEG;
        o.y = m[1] ? acc[i][1] * 0.125f : NEG;
        o.z = m[2] ? acc[i][2] * 0.125f : NEG;
        o.w = m[3] ? acc[i][3] * 0.125f : NEG;
        *(float4*)(probs + ((size_t)bh * 64 + l) * 2048 + s0 + tx * 4) = o;
    }
}

// ---------------- row softmax over S=2048, in place ----------------
__global__ void softmax_kernel(float* __restrict__ probs) {
    size_t row = blockIdx.x;
    float4* p4 = (float4*)(probs + row * 2048);
    int tid = threadIdx.x;
    float4 x0 = p4[tid], x1 = p4[tid + 256];
    float mx = fmaxf(fmaxf(fmaxf(x0.x, x0.y), fmaxf(x0.z, x0.w)),
                     fmaxf(fmaxf(x1.x, x1.y), fmaxf(x1.z, x1.w)));
    __shared__ float red[256];
    red[tid] = mx;
    __syncthreads();
    for (int st = 128; st > 0; st >>= 1) {
        if (tid < st) red[tid] = fmaxf(red[tid], red[tid + st]);
        __syncthreads();
    }
    float m = red[0];
    __syncthreads();
    float e[8];
    e[0] = expf(x0.x - m); e[1] = expf(x0.y - m); e[2] = expf(x0.z - m); e[3] = expf(x0.w - m);
    e[4] = expf(x1.x - m); e[5] = expf(x1.y - m); e[6] = expf(x1.z - m); e[7] = expf(x1.w - m);
    float s = (e[0] + e[1]) + (e[2] + e[3]) + (e[4] + e[5]) + (e[6] + e[7]);
    red[tid] = s;
    __syncthreads();
    for (int st = 128; st > 0; st >>= 1) {
        if (tid < st) red[tid] += red[tid + st];
        __syncthreads();
    }
    float inv = 1.0f / red[0];
    float4 o0, o1;
    o0.x = e[0] * inv; o0.y = e[1] * inv; o0.z = e[2] * inv; o0.w = e[3] * inv;
    o1.x = e[4] * inv; o1.y = e[5] * inv; o1.z = e[6] * inv; o1.w = e[7] * inv;
    p4[tid] = o0;
    p4[tid + 256] = o1;
}

// ---------------- attn = P @ V per (b,h): [64,2048] @ [2048,64] ----------------
__global__ void attn_kernel(const float* __restrict__ probs, const float* __restrict__ vh,
                            float* __restrict__ attn) {
    int bh = blockIdx.x;
    int b = bh >> 4, h = bh & 15;
    __shared__ float Ps[64][68];  // [s_local][l]
    __shared__ float Vs[64][64];  // [s_local][d]
    int tid = threadIdx.x, tx = tid & 15, ty = tid >> 4;
    float acc[4][4] = {};
    for (int s0 = 0; s0 < 2048; s0 += 64) {
#pragma unroll
        for (int it = 0; it < 4; ++it) {
            int v = tid + it * 256;
            int r = v >> 4, cv = (v & 15) * 4;
            float4 pv = *(const float4*)(probs + ((size_t)bh * 64 + r) * 2048 + s0 + cv);
            Ps[cv + 0][r] = pv.x; Ps[cv + 1][r] = pv.y; Ps[cv + 2][r] = pv.z; Ps[cv + 3][r] = pv.w;
            *(float4*)&Vs[r][cv] =
                *(const float4*)(vh + (size_t)(b * 2048 + s0 + r) * 1024 + h * 64 + cv);
        }
        __syncthreads();
#pragma unroll 8
        for (int k = 0; k < 64; ++k) {
            float a[4], bb[4];
            *(float4*)a = *(const float4*)&Ps[k][ty * 4];
            *(float4*)bb = *(const float4*)&Vs[k][tx * 4];
#pragma unroll
            for (int i = 0; i < 4; ++i)
#pragma unroll
                for (int j = 0; j < 4; ++j) acc[i][j] += a[i] * bb[j];
        }
        __syncthreads();
    }
#pragma unroll
    for (int i = 0; i < 4; ++i) {
        int l = ty * 4 + i;
        float4 o;
        o.x = acc[i][0]; o.y = acc[i][1]; o.z = acc[i][2]; o.w = acc[i][3];
        *(float4*)(attn + (size_t)(b * 64 + l) * 1024 + h * 64 + tx * 4) = o;
    }
}

// ---------------- residual add + LayerNorm over D=1024 ----------------
__global__ void add_ln_kernel(const float* __restrict__ a, const float* __restrict__ b2,
                              const float* __restrict__ g, const float* __restrict__ bet,
                              float* __restrict__ out) {
    int row = blockIdx.x, tid = threadIdx.x;
    const float4* a4 = (const float4*)(a + (size_t)row * 1024);
    const float4* b4 = (const float4*)(b2 + (size_t)row * 1024);
    float4 va = a4[tid], vb = b4[tid];
    float4 x;
    x.x = va.x + vb.x; x.y = va.y + vb.y; x.z = va.z + vb.z; x.w = va.w + vb.w;
    float s = (x.x + x.y) + (x.z + x.w);
    float sq = x.x * x.x + x.y * x.y + x.z * x.z + x.w * x.w;
    __shared__ float r1[256], r2[256];
    r1[tid] = s; r2[tid] = sq;
    __syncthreads();
    for (int st = 128; st > 0; st >>= 1) {
        if (tid < st) { r1[tid] += r1[tid + st]; r2[tid] += r2[tid + st]; }
        __syncthreads();
    }
    float mean = r1[0] * (1.0f / 1024.0f);
    float var = r2[0] * (1.0f / 1024.0f) - mean * mean;
    float rstd = rsqrtf(var + 1e-5f);
    float4 gg = ((const float4*)g)[tid], bb = ((const float4*)bet)[tid];
    float4 o;
    o.x = (x.x - mean) * rstd * gg.x + bb.x;
    o.y = (x.y - mean) * rstd * gg.y + bb.y;
    o.z = (x.z - mean) * rstd * gg.z + bb.z;
    o.w = (x.w - mean) * rstd * gg.w + bb.w;
    ((float4*)(out + (size_t)row * 1024))[tid] = o;
}

// ---------------- attn_weights = mean over heads of probs ----------------
__global__ void mean_heads_kernel(const float* __restrict__ probs, float* __restrict__ aw) {
    int i = blockIdx.x * 256 + threadIdx.x;  // [0, 262144) float4 units
    int s4 = i & 511;
    int l = (i >> 9) & 63;
    int b = i >> 15;
    float4 acc = {0.f, 0.f, 0.f, 0.f};
#pragma unroll
    for (int h = 0; h < 16; ++h) {
        float4 p = *(const float4*)(probs + ((size_t)(b * 16 + h) * 64 + l) * 2048 + s4 * 4);
        acc.x += p.x; acc.y += p.y; acc.z += p.z; acc.w += p.w;
    }
    const float inv = 1.0f / 16.0f;
    acc.x *= inv; acc.y *= inv; acc.z *= inv; acc.w *= inv;
    *(float4*)(aw + ((size_t)(b * 64 + l) * 2048) + s4 * 4) = acc;
}

// ---------------- launch ----------------
extern "C" void kernel_launch(void* const* d_in, const int* in_sizes, int n_in,
                              void* d_out, int out_size) {
    (void)in_sizes; (void)n_in; (void)out_size;
    const float* latents = (const float*)d_in[0];
    const float* context = (const float*)d_in[1];
    const int* cmask = (const int*)d_in[2];
    const float* q_w = (const float*)d_in[3];
    const float* q_b = (const float*)d_in[4];
    const float* k_w = (const float*)d_in[5];
    const float* k_b = (const float*)d_in[6];
    const float* v_w = (const float*)d_in[7];
    const float* v_b = (const float*)d_in[8];
    const float* in_wq = (const float*)d_in[9];
    const float* in_bq = (const float*)d_in[10];
    const float* in_wk = (const float*)d_in[11];
    const float* in_bk = (const float*)d_in[12];
    const float* in_wv = (const float*)d_in[13];
    const float* in_bv = (const float*)d_in[14];
    const float* out_w = (const float*)d_in[15];
    const float* out_b = (const float*)d_in[16];
    const float* ln1_g = (const float*)d_in[17];
    const float* ln1_b = (const float*)d_in[18];
    const float* ln2_g = (const float*)d_in[19];
    const float* ln2_b = (const float*)d_in[20];
    const float* ff_w1 = (const float*)d_in[21];
    const float* ff_b1 = (const float*)d_in[22];
    const float* ff_w2 = (const float*)d_in[23];
    const float* ff_b2 = (const float*)d_in[24];

    float* out = (float*)d_out;
    float* aw_out = out + 512 * 1024;

    void* p;
    cudaGetSymbolAddress(&p, g_Wqh);  float* Wqh = (float*)p;
    cudaGetSymbolAddress(&p, g_Wkh);  float* Wkh = (float*)p;
    cudaGetSymbolAddress(&p, g_Wvh);  float* Wvh = (float*)p;
    cudaGetSymbolAddress(&p, g_bqh);  float* bqh = (float*)p;
    cudaGetSymbolAddress(&p, g_bkh);  float* bkh = (float*)p;
    cudaGetSymbolAddress(&p, g_bvh);  float* bvh = (float*)p;
    cudaGetSymbolAddress(&p, g_qh);   float* qh = (float*)p;
    cudaGetSymbolAddress(&p, g_kh);   float* kh = (float*)p;
    cudaGetSymbolAddress(&p, g_vh);   float* vh = (float*)p;
    cudaGetSymbolAddress(&p, g_probs); float* probs = (float*)p;
    cudaGetSymbolAddress(&p, g_attn); float* attn = (float*)p;
    cudaGetSymbolAddress(&p, g_x);    float* xb = (float*)p;
    cudaGetSymbolAddress(&p, g_h1);   float* h1 = (float*)p;

    // Fused weights/biases: Wqh = in_wq@q_w etc. (collapses chained Linears)
    fuse_bias_kernel<<<1024, 256>>>(in_wq, q_b, in_bq, bqh);
    fuse_bias_kernel<<<1024, 256>>>(in_wk, k_b, in_bk, bkh);
    fuse_bias_kernel<<<1024, 256>>>(in_wv, v_b, in_bv, bvh);
    dim3 g88(8, 8);
    gemm_nn_1024<<<g88, 256>>>(in_wq, q_w, Wqh);
    gemm_nn_1024<<<g88, 256>>>(in_wk, k_w, Wkh);
    gemm_nn_1024<<<g88, 256>>>(in_wv, v_w, Wvh);

    // Projections
    gemm_nt<0><<<dim3(8, 4), 256>>>(latents, Wqh, bqh, qh, 512, 1024, 1024);
    gemm_nt<0><<<dim3(8, 128), 256>>>(context, Wkh, bkh, kh, 16384, 1024, 1024);
    gemm_nt<0><<<dim3(8, 128), 256>>>(context, Wvh, bvh, vh, 16384, 1024, 1024);

    // Attention
    scores_kernel<<<dim3(32, 128), 256>>>(qh, kh, cmask, probs);
    softmax_kernel<<<8192, 256>>>(probs);
    attn_kernel<<<128, 256>>>(probs, vh, attn);

    // Out projection (reuse qh buffer for attn_out)
    gemm_nt<0><<<dim3(8, 4), 256>>>(attn, out_w, out_b, qh, 512, 1024, 1024);

    // LN1
    add_ln_kernel<<<512, 256>>>(latents, qh, ln1_g, ln1_b, xb);

    // FFN (exact GELU fused into ff1 epilogue); reuse attn buffer for ff2 out
    gemm_nt<1><<<dim3(32, 4), 256>>>(xb, ff_w1, ff_b1, h1, 512, 4096, 1024);
    gemm_nt<0><<<dim3(8, 4), 256>>>(h1, ff_w2, ff_b2, attn, 512, 1024, 4096);

    // LN2 -> out
    add_ln_kernel<<<512, 256>>>(xb, attn, ln2_g, ln2_b, out);

    // attn_weights -> second output region
    mean_heads_kernel<<<1024, 256>>>(probs, aw_out);
}

// round 4
// speedup vs baseline: 1.3844x; 1.3844x over previous
#include <cuda_runtime.h>
#include <mma.h>
#include <math.h>

using namespace nvcuda;

// Shapes: B=8, L=64, S=2048, D=1024, C=1024, H=16, HD=64

// ---------------- device scratch ----------------
__device__ float g_Wqh[1024 * 1024];
__device__ float g_Wkh[1024 * 1024];
__device__ float g_Wvh[1024 * 1024];
__device__ float g_bqh[1024];
__device__ float g_bkh[1024];
__device__ float g_bvh[1024];
__device__ float g_qh[512 * 1024];      // also reused for attn_out
__device__ float g_kh[16384 * 1024];
__device__ float g_vh[16384 * 1024];
__device__ float g_probs[8192 * 2048];  // [B,H,L,S]
__device__ float g_attn[512 * 1024];    // attn concat; reused for ff2 out
__device__ float g_x[512 * 1024];       // post-LN1
__device__ float g_h1[512 * 4096];      // ff hidden

__device__ __forceinline__ float gelu_exact(float x) {
    return 0.5f * x * (1.0f + erff(x * 0.70710678118654752f));
}

// ---------------- bias fusion: bout[o] = sum_i W[o,i]*bin[i] + badd[o] ----------------
__global__ void fuse_bias_kernel(const float* __restrict__ W, const float* __restrict__ bin,
                                 const float* __restrict__ badd, float* __restrict__ bout) {
    int o = blockIdx.x;
    float s = 0.f;
    for (int i = threadIdx.x; i < 1024; i += 256) s += W[o * 1024 + i] * bin[i];
    __shared__ float red[256];
    red[threadIdx.x] = s;
    __syncthreads();
    for (int st = 128; st > 0; st >>= 1) {
        if (threadIdx.x < st) red[threadIdx.x] += red[threadIdx.x + st];
        __syncthreads();
    }
    if (threadIdx.x == 0) bout[o] = red[0] + badd[o];
}

// ==================== TF32 WMMA GEMM ====================
// NT=1: C[M,N] = A[M,K] @ B[N,K]^T + bias      (B row-major [N,K] -> col_major frag)
// NT=0: C[M,N] = A[M,K] @ B[K,N]   + bias      (B row-major [K,N] -> row_major frag)
// EPI=1: exact GELU after bias. Block tile 128x128, BK=32, 8 warps (64x32 each).
// A smem ld = 40 floats (160B, 32B-aligned rows). B smem ld: NT=40, NN=136.
template <int NT, int EPI, int BIAS>
__global__ void __launch_bounds__(256, 2)
wmma_gemm(const float* __restrict__ A, const float* __restrict__ B,
          const float* __restrict__ bias, float* __restrict__ C,
          int M, int N, int K) {
    __shared__ float As[128 * 40];   // 20 KB
    __shared__ float Bs[128 * 40];   // 20 KB (NN uses 32*136 <= 5120)

    int tid = threadIdx.x;
    int wid = tid >> 5, lane = tid & 31;
    int warpRow = wid >> 2;          // 0..1  -> 64 rows
    int warpCol = wid & 3;           // 0..3  -> 32 cols
    int bm = blockIdx.y * 128, bn = blockIdx.x * 128;

    wmma::fragment<wmma::accumulator, 16, 16, 8, float> acc[4][2];
#pragma unroll
    for (int i = 0; i < 4; ++i)
#pragma unroll
        for (int j = 0; j < 2; ++j) wmma::fill_fragment(acc[i][j], 0.0f);

    for (int k0 = 0; k0 < K; k0 += 32) {
        // load A tile: 128 rows x 32 k  (1024 float4, 4 per thread)
#pragma unroll
        for (int it = 0; it < 4; ++it) {
            int v = tid + it * 256;
            int r = v >> 3, c = (v & 7) * 4;
            *(float4*)&As[r * 40 + c] = *(const float4*)(A + (size_t)(bm + r) * K + k0 + c);
        }
        if (NT) {
            // B tile: 128 n-rows x 32 k
#pragma unroll
            for (int it = 0; it < 4; ++it) {
                int v = tid + it * 256;
                int r = v >> 3, c = (v & 7) * 4;
                *(float4*)&Bs[r * 40 + c] = *(const float4*)(B + (size_t)(bn + r) * K + k0 + c);
            }
        } else {
            // B tile: 32 k-rows x 128 n
#pragma unroll
            for (int it = 0; it < 4; ++it) {
                int v = tid + it * 256;
                int kk = v >> 5, c = (v & 31) * 4;
                *(float4*)&Bs[kk * 136 + c] = *(const float4*)(B + (size_t)(k0 + kk) * N + bn + c);
            }
        }
        __syncthreads();

#pragma unroll
        for (int ks = 0; ks < 4; ++ks) {
            int kk = ks * 8;
            wmma::fragment<wmma::matrix_a, 16, 16, 8, wmma::precision::tf32, wmma::row_major> af[4];
#pragma unroll
            for (int i = 0; i < 4; ++i) {
                wmma::load_matrix_sync(af[i], &As[(warpRow * 64 + i * 16) * 40 + kk], 40);
#pragma unroll
                for (int t = 0; t < af[i].num_elements; ++t)
                    af[i].x[t] = wmma::__float_to_tf32(af[i].x[t]);
            }
            if (NT) {
                wmma::fragment<wmma::matrix_b, 16, 16, 8, wmma::precision::tf32, wmma::col_major> bf[2];
#pragma unroll
                for (int j = 0; j < 2; ++j) {
                    wmma::load_matrix_sync(bf[j], &Bs[(warpCol * 32 + j * 16) * 40 + kk], 40);
#pragma unroll
                    for (int t = 0; t < bf[j].num_elements; ++t)
                        bf[j].x[t] = wmma::__float_to_tf32(bf[j].x[t]);
                }
#pragma unroll
                for (int i = 0; i < 4; ++i)
#pragma unroll
                    for (int j = 0; j < 2; ++j) wmma::mma_sync(acc[i][j], af[i], bf[j], acc[i][j]);
            } else {
                wmma::fragment<wmma::matrix_b, 16, 16, 8, wmma::precision::tf32, wmma::row_major> bf[2];
#pragma unroll
                for (int j = 0; j < 2; ++j) {
                    wmma::load_matrix_sync(bf[j], &Bs[kk * 136 + warpCol * 32 + j * 16], 136);
#pragma unroll
                    for (int t = 0; t < bf[j].num_elements; ++t)
                        bf[j].x[t] = wmma::__float_to_tf32(bf[j].x[t]);
                }
#pragma unroll
                for (int i = 0; i < 4; ++i)
#pragma unroll
                    for (int j = 0; j < 2; ++j) wmma::mma_sync(acc[i][j], af[i], bf[j], acc[i][j]);
            }
        }
        __syncthreads();
    }

    // Epilogue: stage each 16x16 frag through smem (reuse As; per-warp region, ld=24)
    float* st = &As[wid * 384];
#pragma unroll
    for (int i = 0; i < 4; ++i) {
#pragma unroll
        for (int j = 0; j < 2; ++j) {
            wmma::store_matrix_sync(st, acc[i][j], 24, wmma::mem_row_major);
            __syncwarp();
            int row0 = bm + warpRow * 64 + i * 16;
            int col0 = bn + warpCol * 32 + j * 16;
            int r = lane >> 1, cb = (lane & 1) * 8;
            float4 v0 = *(float4*)&st[r * 24 + cb];
            float4 v1 = *(float4*)&st[r * 24 + cb + 4];
            if (BIAS) {
                const float* bp = bias + col0 + cb;
                v0.x += bp[0]; v0.y += bp[1]; v0.z += bp[2]; v0.w += bp[3];
                v1.x += bp[4]; v1.y += bp[5]; v1.z += bp[6]; v1.w += bp[7];
            }
            if (EPI) {
                v0.x = gelu_exact(v0.x); v0.y = gelu_exact(v0.y);
                v0.z = gelu_exact(v0.z); v0.w = gelu_exact(v0.w);
                v1.x = gelu_exact(v1.x); v1.y = gelu_exact(v1.y);
                v1.z = gelu_exact(v1.z); v1.w = gelu_exact(v1.w);
            }
            float* cp = C + (size_t)(row0 + r) * N + col0 + cb;
            *(float4*)cp = v0;
            *(float4*)(cp + 4) = v1;
            __syncwarp();
        }
    }
}

// ---------------- fp32 NT GEMM (kept for the qh projection — protects attn_weights) ----
__global__ void gemm_nt_f32(const float* __restrict__ A, const float* __restrict__ B,
                            const float* __restrict__ bias, float* __restrict__ C,
                            int M, int N, int K) {
    __shared__ float As[16][132];
    __shared__ float Bs[16][132];
    int tid = threadIdx.x;
    int bm = blockIdx.y * 128, bn = blockIdx.x * 128;
    int tx = tid & 15, ty = tid >> 4;
    float acc[8][8] = {};
    const float* Ab = A + (size_t)bm * K;
    const float* Bb = B + (size_t)bn * K;
    for (int k0 = 0; k0 < K; k0 += 16) {
#pragma unroll
        for (int it = 0; it < 2; ++it) {
            int v = tid + it * 256;
            int r = v >> 2, kv = (v & 3) * 4;
            float4 a = *(const float4*)(Ab + (size_t)r * K + k0 + kv);
            As[kv + 0][r] = a.x; As[kv + 1][r] = a.y; As[kv + 2][r] = a.z; As[kv + 3][r] = a.w;
            float4 b = *(const float4*)(Bb + (size_t)r * K + k0 + kv);
            Bs[kv + 0][r] = b.x; Bs[kv + 1][r] = b.y; Bs[kv + 2][r] = b.z; Bs[kv + 3][r] = b.w;
        }
        __syncthreads();
#pragma unroll
        for (int kk = 0; kk < 16; ++kk) {
            float a[8], bb[8];
            *(float4*)a = *(const float4*)&As[kk][ty * 8];
            *(float4*)(a + 4) = *(const float4*)&As[kk][ty * 8 + 4];
            *(float4*)bb = *(const float4*)&Bs[kk][tx * 8];
            *(float4*)(bb + 4) = *(const float4*)&Bs[kk][tx * 8 + 4];
#pragma unroll
            for (int i = 0; i < 8; ++i)
#pragma unroll
                for (int j = 0; j < 8; ++j) acc[i][j] += a[i] * bb[j];
        }
        __syncthreads();
    }
#pragma unroll
    for (int i = 0; i < 8; ++i) {
        int row = bm + ty * 8 + i;
#pragma unroll
        for (int j = 0; j < 8; j += 4) {
            int col = bn + tx * 8 + j;
            float4 o;
            o.x = acc[i][j] + bias[col];
            o.y = acc[i][j + 1] + bias[col + 1];
            o.z = acc[i][j + 2] + bias[col + 2];
            o.w = acc[i][j + 3] + bias[col + 3];
            *(float4*)(C + (size_t)row * N + col) = o;
        }
    }
}

// ---------------- scores: per (b,h), chunk of 64 s; scores = Q K^T / 8, masked ----------
__global__ void scores_kernel(const float* __restrict__ qh, const float* __restrict__ kh,
                              const int* __restrict__ cmask, float* __restrict__ probs) {
    int bh = blockIdx.y;
    int b = bh >> 4, h = bh & 15;
    int s0 = blockIdx.x * 64;
    __shared__ float Qs[64][64];
    __shared__ float Ks[64][68];
    int tid = threadIdx.x;
#pragma unroll
    for (int it = 0; it < 4; ++it) {
        int v = tid + it * 256;
        int r = v >> 4, kv = (v & 15) * 4;
        float4 q = *(const float4*)(qh + (size_t)(b * 64 + r) * 1024 + h * 64 + kv);
        Qs[kv + 0][r] = q.x; Qs[kv + 1][r] = q.y; Qs[kv + 2][r] = q.z; Qs[kv + 3][r] = q.w;
        float4 k = *(const float4*)(kh + (size_t)(b * 2048 + s0 + r) * 1024 + h * 64 + kv);
        Ks[kv + 0][r] = k.x; Ks[kv + 1][r] = k.y; Ks[kv + 2][r] = k.z; Ks[kv + 3][r] = k.w;
    }
    __syncthreads();
    int tx = tid & 15, ty = tid >> 4;
    float acc[4][4] = {};
#pragma unroll 8
    for (int k = 0; k < 64; ++k) {
        float a[4], bb[4];
        *(float4*)a = *(const float4*)&Qs[k][ty * 4];
        *(float4*)bb = *(const float4*)&Ks[k][tx * 4];
#pragma unroll
        for (int i = 0; i < 4; ++i)
#pragma unroll
            for (int j = 0; j < 4; ++j) acc[i][j] += a[i] * bb[j];
    }
    const float NEG = __int_as_float(0xff800000);
    int m[4];
#pragma unroll
    for (int j = 0; j < 4; ++j) m[j] = cmask[b * 2048 + s0 + tx * 4 + j];
#pragma unroll
    for (int i = 0; i < 4; ++i) {
        int l = ty * 4 + i;
        float4 o;
        o.x = m[0] ? acc[i][0] * 0.125f : NEG;
        o.y = m[1] ? acc[i][1] * 0.125f : NEG;
        o.z = m[2] ? acc[i][2] * 0.125f : NEG;
        o.w = m[3] ? acc[i][3] * 0.125f : NEG;
        *(float4*)(probs + ((size_t)bh * 64 + l) * 2048 + s0 + tx * 4) = o;
    }
}

// ---------------- row softmax over S=2048, in place ----------------
__global__ void softmax_kernel(float* __restrict__ probs) {
    size_t row = blockIdx.x;
    float4* p4 = (float4*)(probs + row * 2048);
    int tid = threadIdx.x;
    float4 x0 = p4[tid], x1 = p4[tid + 256];
    float mx = fmaxf(fmaxf(fmaxf(x0.x, x0.y), fmaxf(x0.z, x0.w)),
                     fmaxf(fmaxf(x1.x, x1.y), fmaxf(x1.z, x1.w)));
    __shared__ float red[256];
    red[tid] = mx;
    __syncthreads();
    for (int st = 128; st > 0; st >>= 1) {
        if (tid < st) red[tid] = fmaxf(red[tid], red[tid + st]);
        __syncthreads();
    }
    float m = red[0];
    __syncthreads();
    float e[8];
    e[0] = expf(x0.x - m); e[1] = expf(x0.y - m); e[2] = expf(x0.z - m); e[3] = expf(x0.w - m);
    e[4] = expf(x1.x - m); e[5] = expf(x1.y - m); e[6] = expf(x1.z - m); e[7] = expf(x1.w - m);
    float s = (e[0] + e[1]) + (e[2] + e[3]) + (e[4] + e[5]) + (e[6] + e[7]);
    red[tid] = s;
    __syncthreads();
    for (int st = 128; st > 0; st >>= 1) {
        if (tid < st) red[tid] += red[tid + st];
        __syncthreads();
    }
    float inv = 1.0f / red[0];
    float4 o0, o1;
    o0.x = e[0] * inv; o0.y = e[1] * inv; o0.z = e[2] * inv; o0.w = e[3] * inv;
    o1.x = e[4] * inv; o1.y = e[5] * inv; o1.z = e[6] * inv; o1.w = e[7] * inv;
    p4[tid] = o0;
    p4[tid + 256] = o1;
}

// ---------------- attn = P @ V per (b,h): [64,2048] @ [2048,64] ----------------
__global__ void attn_kernel(const float* __restrict__ probs, const float* __restrict__ vh,
                            float* __restrict__ attn) {
    int bh = blockIdx.x;
    int b = bh >> 4, h = bh & 15;
    __shared__ float Ps[64][68];
    __shared__ float Vs[64][64];
    int tid = threadIdx.x, tx = tid & 15, ty = tid >> 4;
    float acc[4][4] = {};
    for (int s0 = 0; s0 < 2048; s0 += 64) {
#pragma unroll
        for (int it = 0; it < 4; ++it) {
            int v = tid + it * 256;
            int r = v >> 4, cv = (v & 15) * 4;
            float4 pv = *(const float4*)(probs + ((size_t)bh * 64 + r) * 2048 + s0 + cv);
            Ps[cv + 0][r] = pv.x; Ps[cv + 1][r] = pv.y; Ps[cv + 2][r] = pv.z; Ps[cv + 3][r] = pv.w;
            *(float4*)&Vs[r][cv] =
                *(const float4*)(vh + (size_t)(b * 2048 + s0 + r) * 1024 + h * 64 + cv);
        }
        __syncthreads();
#pragma unroll 8
        for (int k = 0; k < 64; ++k) {
            float a[4], bb[4];
            *(float4*)a = *(const float4*)&Ps[k][ty * 4];
            *(float4*)bb = *(const float4*)&Vs[k][tx * 4];
#pragma unroll
            for (int i = 0; i < 4; ++i)
#pragma unroll
                for (int j = 0; j < 4; ++j) acc[i][j] += a[i] * bb[j];
        }
        __syncthreads();
    }
#pragma unroll
    for (int i = 0; i < 4; ++i) {
        int l = ty * 4 + i;
        float4 o;
        o.x = acc[i][0]; o.y = acc[i][1]; o.z = acc[i][2]; o.w = acc[i][3];
        *(float4*)(attn + (size_t)(b * 64 + l) * 1024 + h * 64 + tx * 4) = o;
    }
}

// ---------------- residual add + LayerNorm over D=1024 ----------------
__global__ void add_ln_kernel(const float* __restrict__ a, const float* __restrict__ b2,
                              const float* __restrict__ g, const float* __restrict__ bet,
                              float* __restrict__ out) {
    int row = blockIdx.x, tid = threadIdx.x;
    const float4* a4 = (const float4*)(a + (size_t)row * 1024);
    const float4* b4 = (const float4*)(b2 + (size_t)row * 1024);
    float4 va = a4[tid], vb = b4[tid];
    float4 x;
    x.x = va.x + vb.x; x.y = va.y + vb.y; x.z = va.z + vb.z; x.w = va.w + vb.w;
    float s = (x.x + x.y) + (x.z + x.w);
    float sq = x.x * x.x + x.y * x.y + x.z * x.z + x.w * x.w;
    __shared__ float r1[256], r2[256];
    r1[tid] = s; r2[tid] = sq;
    __syncthreads();
    for (int st = 128; st > 0; st >>= 1) {
        if (tid < st) { r1[tid] += r1[tid + st]; r2[tid] += r2[tid + st]; }
        __syncthreads();
    }
    float mean = r1[0] * (1.0f / 1024.0f);
    float var = r2[0] * (1.0f / 1024.0f) - mean * mean;
    float rstd = rsqrtf(var + 1e-5f);
    float4 gg = ((const float4*)g)[tid], bb = ((const float4*)bet)[tid];
    float4 o;
    o.x = (x.x - mean) * rstd * gg.x + bb.x;
    o.y = (x.y - mean) * rstd * gg.y + bb.y;
    o.z = (x.z - mean) * rstd * gg.z + bb.z;
    o.w = (x.w - mean) * rstd * gg.w + bb.w;
    ((float4*)(out + (size_t)row * 1024))[tid] = o;
}

// ---------------- attn_weights = mean over heads of probs ----------------
__global__ void mean_heads_kernel(const float* __restrict__ probs, float* __restrict__ aw) {
    int i = blockIdx.x * 256 + threadIdx.x;
    int s4 = i & 511;
    int l = (i >> 9) & 63;
    int b = i >> 15;
    float4 acc = {0.f, 0.f, 0.f, 0.f};
#pragma unroll
    for (int h = 0; h < 16; ++h) {
        float4 p = *(const float4*)(probs + ((size_t)(b * 16 + h) * 64 + l) * 2048 + s4 * 4);
        acc.x += p.x; acc.y += p.y; acc.z += p.z; acc.w += p.w;
    }
    const float inv = 1.0f / 16.0f;
    acc.x *= inv; acc.y *= inv; acc.z *= inv; acc.w *= inv;
    *(float4*)(aw + ((size_t)(b * 64 + l) * 2048) + s4 * 4) = acc;
}

// ---------------- launch ----------------
extern "C" void kernel_launch(void* const* d_in, const int* in_sizes, int n_in,
                              void* d_out, int out_size) {
    (void)in_sizes; (void)n_in; (void)out_size;
    const float* latents = (const float*)d_in[0];
    const float* context = (const float*)d_in[1];
    const int* cmask = (const int*)d_in[2];
    const float* q_w = (const float*)d_in[3];
    const float* q_b = (const float*)d_in[4];
    const float* k_w = (const float*)d_in[5];
    const float* k_b = (const float*)d_in[6];
    const float* v_w = (const float*)d_in[7];
    const float* v_b = (const float*)d_in[8];
    const float* in_wq = (const float*)d_in[9];
    const float* in_bq = (const float*)d_in[10];
    const float* in_wk = (const float*)d_in[11];
    const float* in_bk = (const float*)d_in[12];
    const float* in_wv = (const float*)d_in[13];
    const float* in_bv = (const float*)d_in[14];
    const float* out_w = (const float*)d_in[15];
    const float* out_b = (const float*)d_in[16];
    const float* ln1_g = (const float*)d_in[17];
    const float* ln1_b = (const float*)d_in[18];
    const float* ln2_g = (const float*)d_in[19];
    const float* ln2_b = (const float*)d_in[20];
    const float* ff_w1 = (const float*)d_in[21];
    const float* ff_b1 = (const float*)d_in[22];
    const float* ff_w2 = (const float*)d_in[23];
    const float* ff_b2 = (const float*)d_in[24];

    float* out = (float*)d_out;
    float* aw_out = out + 512 * 1024;

    void* p;
    cudaGetSymbolAddress(&p, g_Wqh);  float* Wqh = (float*)p;
    cudaGetSymbolAddress(&p, g_Wkh);  float* Wkh = (float*)p;
    cudaGetSymbolAddress(&p, g_Wvh);  float* Wvh = (float*)p;
    cudaGetSymbolAddress(&p, g_bqh);  float* bqh = (float*)p;
    cudaGetSymbolAddress(&p, g_bkh);  float* bkh = (float*)p;
    cudaGetSymbolAddress(&p, g_bvh);  float* bvh = (float*)p;
    cudaGetSymbolAddress(&p, g_qh);   float* qh = (float*)p;
    cudaGetSymbolAddress(&p, g_kh);   float* kh = (float*)p;
    cudaGetSymbolAddress(&p, g_vh);   float* vh = (float*)p;
    cudaGetSymbolAddress(&p, g_probs); float* probs = (float*)p;
    cudaGetSymbolAddress(&p, g_attn); float* attn = (float*)p;
    cudaGetSymbolAddress(&p, g_x);    float* xb = (float*)p;
    cudaGetSymbolAddress(&p, g_h1);   float* h1 = (float*)p;

    // Fused weights/biases: Wqh = in_wq@q_w etc. (collapses chained Linears) — TF32
    fuse_bias_kernel<<<1024, 256>>>(in_wq, q_b, in_bq, bqh);
    fuse_bias_kernel<<<1024, 256>>>(in_wk, k_b, in_bk, bkh);
    fuse_bias_kernel<<<1024, 256>>>(in_wv, v_b, in_bv, bvh);
    dim3 g88(8, 8);
    wmma_gemm<0, 0, 0><<<g88, 256>>>(in_wq, q_w, nullptr, Wqh, 1024, 1024, 1024);
    wmma_gemm<0, 0, 0><<<g88, 256>>>(in_wk, k_w, nullptr, Wkh, 1024, 1024, 1024);
    wmma_gemm<0, 0, 0><<<g88, 256>>>(in_wv, v_w, nullptr, Wvh, 1024, 1024, 1024);

    // Projections: q in exact fp32 (protects attn_weights error budget), k/v in TF32
    gemm_nt_f32<<<dim3(8, 4), 256>>>(latents, Wqh, bqh, qh, 512, 1024, 1024);
    wmma_gemm<1, 0, 1><<<dim3(8, 128), 256>>>(context, Wkh, bkh, kh, 16384, 1024, 1024);
    wmma_gemm<1, 0, 1><<<dim3(8, 128), 256>>>(context, Wvh, bvh, vh, 16384, 1024, 1024);

    // Attention (fp32)
    scores_kernel<<<dim3(32, 128), 256>>>(qh, kh, cmask, probs);
    softmax_kernel<<<8192, 256>>>(probs);
    attn_kernel<<<128, 256>>>(probs, vh, attn);

    // Out projection (TF32; reuse qh buffer for attn_out)
    wmma_gemm<1, 0, 1><<<dim3(8, 4), 256>>>(attn, out_w, out_b, qh, 512, 1024, 1024);

    // LN1
    add_ln_kernel<<<512, 256>>>(latents, qh, ln1_g, ln1_b, xb);

    // FFN (TF32; exact GELU fused into ff1 epilogue); reuse attn buffer for ff2 out
    wmma_gemm<1, 1, 1><<<dim3(32, 4), 256>>>(xb, ff_w1, ff_b1, h1, 512, 4096, 1024);
    wmma_gemm<1, 0, 1><<<dim3(8, 4), 256>>>(h1, ff_w2, ff_b2, attn, 512, 1024, 4096);

    // LN2 -> out
    add_ln_kernel<<<512, 256>>>(xb, attn, ln2_g, ln2_b, out);

    // attn_weights -> second output region
    mean_heads_kernel<<<1024, 256>>>(probs, aw_out);
}

// round 5
// speedup vs baseline: 1.6901x; 1.2208x over previous
#include <cuda_runtime.h>
#include <mma.h>
#include <math.h>
#include <stdint.h>

using namespace nvcuda;

// Shapes: B=8, L=64, S=2048, D=1024, C=1024, H=16, HD=64

// ---------------- device scratch ----------------
__device__ float g_fuse6[6 * 1024 * 1024];   // rounded fusion inputs
__device__ float g_ctx_r[16384 * 1024];      // rounded context
__device__ float g_lat_r[512 * 1024];        // rounded latents
__device__ float g_outw_r[1024 * 1024];
__device__ float g_ffw1_r[4096 * 1024];
__device__ float g_ffw2_r[1024 * 4096];
__device__ float g_Wq[1024 * 1024];          // fused+rounded q weight
__device__ float g_Wkv[2048 * 1024];         // fused+rounded k|v weights
__device__ float g_bq[1024];
__device__ float g_bkv[2048];
__device__ float g_qh[512 * 1024];           // q heads; reused for attn_out
__device__ float g_kv[16384 * 2048];         // kh | vh interleaved per row
__device__ float g_probs[8192 * 2048];       // [B,H,L,S]
__device__ float g_attn[512 * 1024];         // attn concat (rounded); reused for ff2 out
__device__ float g_x[512 * 1024];            // post-LN1 exact
__device__ float g_xr[512 * 1024];           // post-LN1 rounded
__device__ float g_h1[512 * 4096];           // ff hidden (rounded)

__device__ __forceinline__ float gelu_exact(float x) {
    return 0.5f * x * (1.0f + erff(x * 0.70710678118654752f));
}
__device__ __forceinline__ float rtf(float x) {
    float y;
    asm("cvt.rna.tf32.f32 %0, %1;" : "=f"(y) : "f"(x));
    return y;
}
__device__ __forceinline__ void cp16(uint32_t dst, const void* src) {
    asm volatile("cp.async.cg.shared.global [%0], [%1], 16;\n" ::"r"(dst), "l"(src));
}
#define CP_COMMIT() asm volatile("cp.async.commit_group;\n" ::)
#define CP_WAIT(n) asm volatile("cp.async.wait_group %0;\n" ::"n"(n))

// ---------------- rounding kernels ----------------
__global__ void round_tf32_kernel(const float4* __restrict__ in, float4* __restrict__ out, int n4) {
    int i = blockIdx.x * 256 + threadIdx.x;
    if (i < n4) {
        float4 v = in[i];
        v.x = rtf(v.x); v.y = rtf(v.y); v.z = rtf(v.z); v.w = rtf(v.w);
        out[i] = v;
    }
}
__global__ void round6_kernel(const float4* a0, const float4* a1, const float4* a2,
                              const float4* a3, const float4* a4, const float4* a5,
                              float4* __restrict__ out) {
    const float4* srcs[6] = {a0, a1, a2, a3, a4, a5};
    int z = blockIdx.y;
    int i = blockIdx.x * 256 + threadIdx.x;  // 0..262143
    float4 v = srcs[z][i];
    v.x = rtf(v.x); v.y = rtf(v.y); v.z = rtf(v.z); v.w = rtf(v.w);
    out[(size_t)z * 262144 + i] = v;
}

// ---------------- bias fusion: bout[o] = sum_i W[o,i]*bin[i] + badd[o] ----------------
__global__ void fuse_bias_kernel(const float* __restrict__ W, const float* __restrict__ bin,
                                 const float* __restrict__ badd, float* __restrict__ bout) {
    int o = blockIdx.x;
    float s = 0.f;
    for (int i = threadIdx.x; i < 1024; i += 256) s += W[o * 1024 + i] * bin[i];
    __shared__ float red[256];
    red[threadIdx.x] = s;
    __syncthreads();
    for (int st = 128; st > 0; st >>= 1) {
        if (threadIdx.x < st) red[threadIdx.x] += red[threadIdx.x + st];
        __syncthreads();
    }
    if (threadIdx.x == 0) bout[o] = red[0] + badd[o];
}

// ==================== TF32 WMMA GEMM, cp.async double-buffered ====================
// Inputs MUST be pre-rounded to tf32 (no in-fragment conversion).
// NT=1: C[M,N]=A[M,K]@B[N,K]^T+bias   NT=0: C=A[M,K]@B[K,N]+bias
// EPI: exact GELU. RND: round outputs to tf32.
// Block tile 128x128, BK=32, 8 warps (64x32 each). Dyn smem 80KB:
//   As stage stride 5120 fl (ld 40), Bs stage stride 5120 (NT ld 40 / NN ld 136).
template <int NT, int EPI, int BIAS, int RND>
__device__ __forceinline__ void gemm_body(const float* __restrict__ A, const float* __restrict__ B,
                                          const float* __restrict__ bias, float* __restrict__ C,
                                          int M, int N, int K, float* sm) {
    int tid = threadIdx.x;
    int wid = tid >> 5, lane = tid & 31;
    int warpRow = wid >> 2, warpCol = wid & 3;
    int bm = blockIdx.y * 128, bn = blockIdx.x * 128;

    uint32_t s_base = (uint32_t)__cvta_generic_to_shared(sm);
    // per-thread load coords
    int ra = tid >> 3, ca = (tid & 7) * 4;          // A & NT-B: 32 rows per it
    int kb = tid >> 5, cb = (tid & 31) * 4;         // NN-B: 8 k-rows per it

    wmma::fragment<wmma::accumulator, 16, 16, 8, float> acc[4][2];
#pragma unroll
    for (int i = 0; i < 4; ++i)
#pragma unroll
        for (int j = 0; j < 2; ++j) wmma::fill_fragment(acc[i][j], 0.0f);

    const int KT = K >> 5;

    // -------- issue loads for (stage, k0) --------
    auto issue = [&](int stage, int k0) {
        uint32_t as = s_base + (uint32_t)(stage * 5120) * 4;
        uint32_t bs = s_base + (uint32_t)(10240 + stage * 5120) * 4;
#pragma unroll
        for (int it = 0; it < 4; ++it) {
            int r = ra + it * 32;
            cp16(as + (uint32_t)(r * 40 + ca) * 4, A + (size_t)(bm + r) * K + k0 + ca);
        }
        if (NT) {
#pragma unroll
            for (int it = 0; it < 4; ++it) {
                int r = ra + it * 32;
                cp16(bs + (uint32_t)(r * 40 + ca) * 4, B + (size_t)(bn + r) * K + k0 + ca);
            }
        } else {
#pragma unroll
            for (int it = 0; it < 4; ++it) {
                int kk = kb + it * 8;
                cp16(bs + (uint32_t)(kk * 136 + cb) * 4, B + (size_t)(k0 + kk) * N + bn + cb);
            }
        }
        CP_COMMIT();
    };

    issue(0, 0);
    for (int kt = 0; kt < KT; ++kt) {
        int stage = kt & 1;
        if (kt + 1 < KT) {
            issue(stage ^ 1, (kt + 1) * 32);
            CP_WAIT(1);
        } else {
            CP_WAIT(0);
        }
        __syncthreads();
        float* As = sm + stage * 5120;
        float* Bs = sm + 10240 + stage * 5120;
#pragma unroll
        for (int ks = 0; ks < 4; ++ks) {
            int kk = ks * 8;
            wmma::fragment<wmma::matrix_a, 16, 16, 8, wmma::precision::tf32, wmma::row_major> af[4];
#pragma unroll
            for (int i = 0; i < 4; ++i)
                wmma::load_matrix_sync(af[i], &As[(warpRow * 64 + i * 16) * 40 + kk], 40);
            if (NT) {
                wmma::fragment<wmma::matrix_b, 16, 16, 8, wmma::precision::tf32, wmma::col_major> bf[2];
#pragma unroll
                for (int j = 0; j < 2; ++j)
                    wmma::load_matrix_sync(bf[j], &Bs[(warpCol * 32 + j * 16) * 40 + kk], 40);
#pragma unroll
                for (int i = 0; i < 4; ++i)
#pragma unroll
                    for (int j = 0; j < 2; ++j) wmma::mma_sync(acc[i][j], af[i], bf[j], acc[i][j]);
            } else {
                wmma::fragment<wmma::matrix_b, 16, 16, 8, wmma::precision::tf32, wmma::row_major> bf[2];
#pragma unroll
                for (int j = 0; j < 2; ++j)
                    wmma::load_matrix_sync(bf[j], &Bs[kk * 136 + warpCol * 32 + j * 16], 136);
#pragma unroll
                for (int i = 0; i < 4; ++i)
#pragma unroll
                    for (int j = 0; j < 2; ++j) wmma::mma_sync(acc[i][j], af[i], bf[j], acc[i][j]);
            }
        }
        __syncthreads();
    }

    // Epilogue: stage each 16x16 frag through smem (per-warp region, ld=24)
    float* st = &sm[wid * 384];
#pragma unroll
    for (int i = 0; i < 4; ++i) {
#pragma unroll
        for (int j = 0; j < 2; ++j) {
            wmma::store_matrix_sync(st, acc[i][j], 24, wmma::mem_row_major);
            __syncwarp();
            int row0 = bm + warpRow * 64 + i * 16;
            int col0 = bn + warpCol * 32 + j * 16;
            int r = lane >> 1, c8 = (lane & 1) * 8;
            float4 v0 = *(float4*)&st[r * 24 + c8];
            float4 v1 = *(float4*)&st[r * 24 + c8 + 4];
            if (BIAS) {
                const float* bp = bias + col0 + c8;
                v0.x += bp[0]; v0.y += bp[1]; v0.z += bp[2]; v0.w += bp[3];
                v1.x += bp[4]; v1.y += bp[5]; v1.z += bp[6]; v1.w += bp[7];
            }
            if (EPI) {
                v0.x = gelu_exact(v0.x); v0.y = gelu_exact(v0.y);
                v0.z = gelu_exact(v0.z); v0.w = gelu_exact(v0.w);
                v1.x = gelu_exact(v1.x); v1.y = gelu_exact(v1.y);
                v1.z = gelu_exact(v1.z); v1.w = gelu_exact(v1.w);
            }
            if (RND) {
                v0.x = rtf(v0.x); v0.y = rtf(v0.y); v0.z = rtf(v0.z); v0.w = rtf(v0.w);
                v1.x = rtf(v1.x); v1.y = rtf(v1.y); v1.z = rtf(v1.z); v1.w = rtf(v1.w);
            }
            float* cp = C + (size_t)(row0 + r) * N + col0 + c8;
            *(float4*)cp = v0;
            *(float4*)(cp + 4) = v1;
            __syncwarp();
        }
    }
}

template <int NT, int EPI, int BIAS, int RND>
__global__ void __launch_bounds__(256, 2)
wmma_gemm(const float* __restrict__ A, const float* __restrict__ B,
          const float* __restrict__ bias, float* __restrict__ C, int M, int N, int K) {
    extern __shared__ float sm[];
    gemm_body<NT, EPI, BIAS, RND>(A, B, bias, C, M, N, K, sm);
}

// batched 1024^3 NN weight-fusion GEMMs (z selects), outputs rounded
__global__ void __launch_bounds__(256, 2)
wmma_gemm_fuse3(const float* A0, const float* B0, float* C0,
                const float* A1, const float* B1, float* C1,
                const float* A2, const float* B2, float* C2) {
    extern __shared__ float sm[];
    if (blockIdx.z == 0)
        gemm_body<0, 0, 0, 1>(A0, B0, nullptr, C0, 1024, 1024, 1024, sm);
    else if (blockIdx.z == 1)
        gemm_body<0, 0, 0, 1>(A1, B1, nullptr, C1, 1024, 1024, 1024, sm);
    else
        gemm_body<0, 0, 0, 1>(A2, B2, nullptr, C2, 1024, 1024, 1024, sm);
}

// ---------------- scores: per (b,h), 64-s chunk; scores = Q K^T / 8, masked ----------
__global__ void scores_kernel(const float* __restrict__ qh, const float* __restrict__ kv,
                              const int* __restrict__ cmask, float* __restrict__ probs) {
    int bh = blockIdx.y;
    int b = bh >> 4, h = bh & 15;
    int s0 = blockIdx.x * 64;
    __shared__ float Qs[64][64];
    __shared__ float Ks[64][68];
    int tid = threadIdx.x;
#pragma unroll
    for (int it = 0; it < 4; ++it) {
        int v = tid + it * 256;
        int r = v >> 4, k4 = (v & 15) * 4;
        float4 q = *(const float4*)(qh + (size_t)(b * 64 + r) * 1024 + h * 64 + k4);
        Qs[k4 + 0][r] = q.x; Qs[k4 + 1][r] = q.y; Qs[k4 + 2][r] = q.z; Qs[k4 + 3][r] = q.w;
        float4 k = *(const float4*)(kv + (size_t)(b * 2048 + s0 + r) * 2048 + h * 64 + k4);
        Ks[k4 + 0][r] = k.x; Ks[k4 + 1][r] = k.y; Ks[k4 + 2][r] = k.z; Ks[k4 + 3][r] = k.w;
    }
    __syncthreads();
    int tx = tid & 15, ty = tid >> 4;
    float acc[4][4] = {};
#pragma unroll 8
    for (int k = 0; k < 64; ++k) {
        float a[4], bb[4];
        *(float4*)a = *(const float4*)&Qs[k][ty * 4];
        *(float4*)bb = *(const float4*)&Ks[k][tx * 4];
#pragma unroll
        for (int i = 0; i < 4; ++i)
#pragma unroll
            for (int j = 0; j < 4; ++j) acc[i][j] += a[i] * bb[j];
    }
    const float NEG = __int_as_float(0xff800000);
    int m[4];
#pragma unroll
    for (int j = 0; j < 4; ++j) m[j] = cmask[b * 2048 + s0 + tx * 4 + j];
#pragma unroll
    for (int i = 0; i < 4; ++i) {
        int l = ty * 4 + i;
        float4 o;
        o.x = m[0] ? acc[i][0] * 0.125f : NEG;
        o.y = m[1] ? acc[i][1] * 0.125f : NEG;
        o.z = m[2] ? acc[i][2] * 0.125f : NEG;
        o.w = m[3] ? acc[i][3] * 0.125f : NEG;
        *(float4*)(probs + ((size_t)bh * 64 + l) * 2048 + s0 + tx * 4) = o;
    }
}

// ---------------- row softmax over S=2048, in place ----------------
__global__ void softmax_kernel(float* __restrict__ probs) {
    size_t row = blockIdx.x;
    float4* p4 = (float4*)(probs + row * 2048);
    int tid = threadIdx.x;
    float4 x0 = p4[tid], x1 = p4[tid + 256];
    float mx = fmaxf(fmaxf(fmaxf(x0.x, x0.y), fmaxf(x0.z, x0.w)),
                     fmaxf(fmaxf(x1.x, x1.y), fmaxf(x1.z, x1.w)));
    __shared__ float red[256];
    red[tid] = mx;
    __syncthreads();
    for (int st = 128; st > 0; st >>= 1) {
        if (tid < st) red[tid] = fmaxf(red[tid], red[tid + st]);
        __syncthreads();
    }
    float m = red[0];
    __syncthreads();
    float e[8];
    e[0] = expf(x0.x - m); e[1] = expf(x0.y - m); e[2] = expf(x0.z - m); e[3] = expf(x0.w - m);
    e[4] = expf(x1.x - m); e[5] = expf(x1.y - m); e[6] = expf(x1.z - m); e[7] = expf(x1.w - m);
    float s = (e[0] + e[1]) + (e[2] + e[3]) + (e[4] + e[5]) + (e[6] + e[7]);
    red[tid] = s;
    __syncthreads();
    for (int st = 128; st > 0; st >>= 1) {
        if (tid < st) red[tid] += red[tid + st];
        __syncthreads();
    }
    float inv = 1.0f / red[0];
    float4 o0, o1;
    o0.x = e[0] * inv; o0.y = e[1] * inv; o0.z = e[2] * inv; o0.w = e[3] * inv;
    o1.x = e[4] * inv; o1.y = e[5] * inv; o1.z = e[6] * inv; o1.w = e[7] * inv;
    p4[tid] = o0;
    p4[tid + 256] = o1;
}

// ---------------- attn = P @ V per (b,h); output rounded to tf32 ----------------
__global__ void attn_kernel(const float* __restrict__ probs, const float* __restrict__ kv,
                            float* __restrict__ attn) {
    int bh = blockIdx.x;
    int b = bh >> 4, h = bh & 15;
    __shared__ float Ps[64][68];
    __shared__ float Vs[64][64];
    int tid = threadIdx.x, tx = tid & 15, ty = tid >> 4;
    float acc[4][4] = {};
    for (int s0 = 0; s0 < 2048; s0 += 64) {
#pragma unroll
        for (int it = 0; it < 4; ++it) {
            int v = tid + it * 256;
            int r = v >> 4, cv = (v & 15) * 4;
            float4 pv = *(const float4*)(probs + ((size_t)bh * 64 + r) * 2048 + s0 + cv);
            Ps[cv + 0][r] = pv.x; Ps[cv + 1][r] = pv.y; Ps[cv + 2][r] = pv.z; Ps[cv + 3][r] = pv.w;
            *(float4*)&Vs[r][cv] =
                *(const float4*)(kv + (size_t)(b * 2048 + s0 + r) * 2048 + 1024 + h * 64 + cv);
        }
        __syncthreads();
#pragma unroll 8
        for (int k = 0; k < 64; ++k) {
            float a[4], bb[4];
            *(float4*)a = *(const float4*)&Ps[k][ty * 4];
            *(float4*)bb = *(const float4*)&Vs[k][tx * 4];
#pragma unroll
            for (int i = 0; i < 4; ++i)
#pragma unroll
                for (int j = 0; j < 4; ++j) acc[i][j] += a[i] * bb[j];
        }
        __syncthreads();
    }
#pragma unroll
    for (int i = 0; i < 4; ++i) {
        int l = ty * 4 + i;
        float4 o;
        o.x = rtf(acc[i][0]); o.y = rtf(acc[i][1]); o.z = rtf(acc[i][2]); o.w = rtf(acc[i][3]);
        *(float4*)(attn + (size_t)(b * 64 + l) * 1024 + h * 64 + tx * 4) = o;
    }
}

// ---------------- residual add + LayerNorm over D=1024 (optional rounded copy) --------
template <int WR>
__global__ void add_ln_kernel(const float* __restrict__ a, const float* __restrict__ b2,
                              const float* __restrict__ g, const float* __restrict__ bet,
                              float* __restrict__ out, float* __restrict__ out_r) {
    int row = blockIdx.x, tid = threadIdx.x;
    const float4* a4 = (const float4*)(a + (size_t)row * 1024);
    const float4* b4 = (const float4*)(b2 + (size_t)row * 1024);
    float4 va = a4[tid], vb = b4[tid];
    float4 x;
    x.x = va.x + vb.x; x.y = va.y + vb.y; x.z = va.z + vb.z; x.w = va.w + vb.w;
    float s = (x.x + x.y) + (x.z + x.w);
    float sq = x.x * x.x + x.y * x.y + x.z * x.z + x.w * x.w;
    __shared__ float r1[256], r2[256];
    r1[tid] = s; r2[tid] = sq;
    __syncthreads();
    for (int st = 128; st > 0; st >>= 1) {
        if (tid < st) { r1[tid] += r1[tid + st]; r2[tid] += r2[tid + st]; }
        __syncthreads();
    }
    float mean = r1[0] * (1.0f / 1024.0f);
    float var = r2[0] * (1.0f / 1024.0f) - mean * mean;
    float rstd = rsqrtf(var + 1e-5f);
    float4 gg = ((const float4*)g)[tid], bb = ((const float4*)bet)[tid];
    float4 o;
    o.x = (x.x - mean) * rstd * gg.x + bb.x;
    o.y = (x.y - mean) * rstd * gg.y + bb.y;
    o.z = (x.z - mean) * rstd * gg.z + bb.z;
    o.w = (x.w - mean) * rstd * gg.w + bb.w;
    ((float4*)(out + (size_t)row * 1024))[tid] = o;
    if (WR) {
        float4 q;
        q.x = rtf(o.x); q.y = rtf(o.y); q.z = rtf(o.z); q.w = rtf(o.w);
        ((float4*)(out_r + (size_t)row * 1024))[tid] = q;
    }
}

// ---------------- attn_weights = mean over heads of probs ----------------
__global__ void mean_heads_kernel(const float* __restrict__ probs, float* __restrict__ aw) {
    int i = blockIdx.x * 256 + threadIdx.x;
    int s4 = i & 511;
    int l = (i >> 9) & 63;
    int b = i >> 15;
    float4 acc = {0.f, 0.f, 0.f, 0.f};
#pragma unroll
    for (int h = 0; h < 16; ++h) {
        float4 p = *(const float4*)(probs + ((size_t)(b * 16 + h) * 64 + l) * 2048 + s4 * 4);
        acc.x += p.x; acc.y += p.y; acc.z += p.z; acc.w += p.w;
    }
    const float inv = 1.0f / 16.0f;
    acc.x *= inv; acc.y *= inv; acc.z *= inv; acc.w *= inv;
    *(float4*)(aw + ((size_t)(b * 64 + l) * 2048) + s4 * 4) = acc;
}

// ---------------- launch ----------------
extern "C" void kernel_launch(void* const* d_in, const int* in_sizes, int n_in,
                              void* d_out, int out_size) {
    (void)in_sizes; (void)n_in; (void)out_size;
    const float* latents = (const float*)d_in[0];
    const float* context = (const float*)d_in[1];
    const int* cmask = (const int*)d_in[2];
    const float* q_w = (const float*)d_in[3];
    const float* q_b = (const float*)d_in[4];
    const float* k_w = (const float*)d_in[5];
    const float* k_b = (const float*)d_in[6];
    const float* v_w = (const float*)d_in[7];
    const float* v_b = (const float*)d_in[8];
    const float* in_wq = (const float*)d_in[9];
    const float* in_bq = (const float*)d_in[10];
    const float* in_wk = (const float*)d_in[11];
    const float* in_bk = (const float*)d_in[12];
    const float* in_wv = (const float*)d_in[13];
    const float* in_bv = (const float*)d_in[14];
    const float* out_w = (const float*)d_in[15];
    const float* out_b = (const float*)d_in[16];
    const float* ln1_g = (const float*)d_in[17];
    const float* ln1_b = (const float*)d_in[18];
    const float* ln2_g = (const float*)d_in[19];
    const float* ln2_b = (const float*)d_in[20];
    const float* ff_w1 = (const float*)d_in[21];
    const float* ff_b1 = (const float*)d_in[22];
    const float* ff_w2 = (const float*)d_in[23];
    const float* ff_b2 = (const float*)d_in[24];

    float* out = (float*)d_out;
    float* aw_out = out + 512 * 1024;

    void* p;
    cudaGetSymbolAddress(&p, g_fuse6);  float* fuse6 = (float*)p;
    cudaGetSymbolAddress(&p, g_ctx_r);  float* ctx_r = (float*)p;
    cudaGetSymbolAddress(&p, g_lat_r);  float* lat_r = (float*)p;
    cudaGetSymbolAddress(&p, g_outw_r); float* outw_r = (float*)p;
    cudaGetSymbolAddress(&p, g_ffw1_r); float* ffw1_r = (float*)p;
    cudaGetSymbolAddress(&p, g_ffw2_r); float* ffw2_r = (float*)p;
    cudaGetSymbolAddress(&p, g_Wq);     float* Wq = (float*)p;
    cudaGetSymbolAddress(&p, g_Wkv);    float* Wkv = (float*)p;
    cudaGetSymbolAddress(&p, g_bq);     float* bq = (float*)p;
    cudaGetSymbolAddress(&p, g_bkv);    float* bkv = (float*)p;
    cudaGetSymbolAddress(&p, g_qh);     float* qh = (float*)p;
    cudaGetSymbolAddress(&p, g_kv);     float* kvb = (float*)p;
    cudaGetSymbolAddress(&p, g_probs);  float* probs = (float*)p;
    cudaGetSymbolAddress(&p, g_attn);   float* attn = (float*)p;
    cudaGetSymbolAddress(&p, g_x);      float* xb = (float*)p;
    cudaGetSymbolAddress(&p, g_xr);     float* xr = (float*)p;
    cudaGetSymbolAddress(&p, g_h1);     float* h1 = (float*)p;

    const int SMEM = 81920;
    cudaFuncSetAttribute(wmma_gemm_fuse3, cudaFuncAttributeMaxDynamicSharedMemorySize, SMEM);
    cudaFuncSetAttribute(wmma_gemm<1, 0, 1, 1>, cudaFuncAttributeMaxDynamicSharedMemorySize, SMEM);
    cudaFuncSetAttribute(wmma_gemm<1, 0, 1, 0>, cudaFuncAttributeMaxDynamicSharedMemorySize, SMEM);
    cudaFuncSetAttribute(wmma_gemm<1, 1, 1, 1>, cudaFuncAttributeMaxDynamicSharedMemorySize, SMEM);

    // ---- pre-round operands to tf32 (RNE) ----
    round6_kernel<<<dim3(1024, 6), 256>>>((const float4*)in_wq, (const float4*)q_w,
                                          (const float4*)in_wk, (const float4*)k_w,
                                          (const float4*)in_wv, (const float4*)v_w,
                                          (float4*)fuse6);
    round_tf32_kernel<<<16384, 256>>>((const float4*)context, (float4*)ctx_r, 4194304);
    round_tf32_kernel<<<512, 256>>>((const float4*)latents, (float4*)lat_r, 131072);
    round_tf32_kernel<<<1024, 256>>>((const float4*)out_w, (float4*)outw_r, 262144);
    round_tf32_kernel<<<4096, 256>>>((const float4*)ff_w1, (float4*)ffw1_r, 1048576);
    round_tf32_kernel<<<4096, 256>>>((const float4*)ff_w2, (float4*)ffw2_r, 1048576);

    // ---- fused weights/biases (Wqh = in_wq@q_w, etc.), batched ----
    fuse_bias_kernel<<<1024, 256>>>(in_wq, q_b, in_bq, bq);
    fuse_bias_kernel<<<1024, 256>>>(in_wk, k_b, in_bk, bkv);
    fuse_bias_kernel<<<1024, 256>>>(in_wv, v_b, in_bv, bkv + 1024);
    const size_t MM = 1024 * 1024;
    wmma_gemm_fuse3<<<dim3(8, 8, 3), 256, SMEM>>>(
        fuse6 + 0 * MM, fuse6 + 1 * MM, Wq,
        fuse6 + 2 * MM, fuse6 + 3 * MM, Wkv,
        fuse6 + 4 * MM, fuse6 + 5 * MM, Wkv + 1024 * 1024);

    // ---- projections ----
    wmma_gemm<1, 0, 1, 0><<<dim3(8, 4), 256, SMEM>>>(lat_r, Wq, bq, qh, 512, 1024, 1024);
    wmma_gemm<1, 0, 1, 1><<<dim3(16, 128), 256, SMEM>>>(ctx_r, Wkv, bkv, kvb, 16384, 2048, 1024);

    // ---- attention (fp32) ----
    scores_kernel<<<dim3(32, 128), 256>>>(qh, kvb, cmask, probs);
    softmax_kernel<<<8192, 256>>>(probs);
    attn_kernel<<<128, 256>>>(probs, kvb, attn);

    // ---- out projection (reuse qh for attn_out) ----
    wmma_gemm<1, 0, 1, 0><<<dim3(8, 4), 256, SMEM>>>(attn, outw_r, out_b, qh, 512, 1024, 1024);

    // ---- LN1 (exact + rounded copy) ----
    add_ln_kernel<1><<<512, 256>>>(latents, qh, ln1_g, ln1_b, xb, xr);

    // ---- FFN ----
    wmma_gemm<1, 1, 1, 1><<<dim3(32, 4), 256, SMEM>>>(xr, ffw1_r, ff_b1, h1, 512, 4096, 1024);
    wmma_gemm<1, 0, 1, 0><<<dim3(8, 4), 256, SMEM>>>(h1, ffw2_r, ff_b2, attn, 512, 1024, 4096);

    // ---- LN2 -> out ----
    add_ln_kernel<0><<<512, 256>>>(xb, attn, ln2_g, ln2_b, out, nullptr);

    // ---- attn_weights -> second output region ----
    mean_heads_kernel<<<1024, 256>>>(probs, aw_out);
}

// round 6
// speedup vs baseline: 1.8576x; 1.0991x over previous
#include <cuda_runtime.h>
#include <mma.h>
#include <math.h>
#include <stdint.h>

using namespace nvcuda;

// Shapes: B=8, L=64, S=2048, D=1024, C=1024, H=16, HD=64

// ---------------- device scratch ----------------
__device__ float g_fuse6[6 * 1024 * 1024];   // rounded fusion inputs
__device__ float g_ctx_r[16384 * 1024];      // rounded context
__device__ float g_lat_r[512 * 1024];        // rounded latents
__device__ float g_outw_r[1024 * 1024];
__device__ float g_ffw1_r[4096 * 1024];
__device__ float g_ffw2_r[1024 * 4096];
__device__ float g_Wq[1024 * 1024];          // fused+rounded q weight
__device__ float g_Wkv[2048 * 1024];         // fused+rounded k|v weights
__device__ float g_bq[1024];
__device__ float g_bkv[2048];
__device__ float g_qh[512 * 1024];           // q heads (rounded); reused for attn_out
__device__ float g_kv[16384 * 2048];         // kh | vh interleaved per row (rounded)
__device__ float g_probs[8192 * 2048];       // [B,H,L,S] (rounded post-softmax)
__device__ float g_attn[512 * 1024];         // attn concat (rounded); reused for ff2 out
__device__ float g_x[512 * 1024];            // post-LN1 exact
__device__ float g_xr[512 * 1024];           // post-LN1 rounded
__device__ float g_h1[512 * 4096];           // ff hidden (rounded)

__device__ __forceinline__ float gelu_exact(float x) {
    return 0.5f * x * (1.0f + erff(x * 0.70710678118654752f));
}
__device__ __forceinline__ float rtf(float x) {
    float y;
    asm("cvt.rna.tf32.f32 %0, %1;" : "=f"(y) : "f"(x));
    return y;
}
__device__ __forceinline__ void cp16(uint32_t dst, const void* src) {
    asm volatile("cp.async.cg.shared.global [%0], [%1], 16;\n" ::"r"(dst), "l"(src));
}
#define CP_COMMIT() asm volatile("cp.async.commit_group;\n" ::)
#define CP_WAIT(n) asm volatile("cp.async.wait_group %0;\n" ::"n"(n))

// ---------------- rounding kernels ----------------
__global__ void round_tf32_kernel(const float4* __restrict__ in, float4* __restrict__ out, int n4) {
    int i = blockIdx.x * 256 + threadIdx.x;
    if (i < n4) {
        float4 v = in[i];
        v.x = rtf(v.x); v.y = rtf(v.y); v.z = rtf(v.z); v.w = rtf(v.w);
        out[i] = v;
    }
}
__global__ void round6_kernel(const float4* a0, const float4* a1, const float4* a2,
                              const float4* a3, const float4* a4, const float4* a5,
                              float4* __restrict__ out) {
    const float4* srcs[6] = {a0, a1, a2, a3, a4, a5};
    int z = blockIdx.y;
    int i = blockIdx.x * 256 + threadIdx.x;
    float4 v = srcs[z][i];
    v.x = rtf(v.x); v.y = rtf(v.y); v.z = rtf(v.z); v.w = rtf(v.w);
    out[(size_t)z * 262144 + i] = v;
}

// ---------------- bias fusion ----------------
__global__ void fuse_bias_kernel(const float* __restrict__ W, const float* __restrict__ bin,
                                 const float* __restrict__ badd, float* __restrict__ bout) {
    int o = blockIdx.x;
    float s = 0.f;
    for (int i = threadIdx.x; i < 1024; i += 256) s += W[o * 1024 + i] * bin[i];
    __shared__ float red[256];
    red[threadIdx.x] = s;
    __syncthreads();
    for (int st = 128; st > 0; st >>= 1) {
        if (threadIdx.x < st) red[threadIdx.x] += red[threadIdx.x + st];
        __syncthreads();
    }
    if (threadIdx.x == 0) bout[o] = red[0] + badd[o];
}

// ==================== TF32 WMMA GEMM 128x128 (generic) ====================
template <int NT, int EPI, int BIAS, int RND>
__device__ __forceinline__ void gemm_body(const float* __restrict__ A, const float* __restrict__ B,
                                          const float* __restrict__ bias, float* __restrict__ C,
                                          int M, int N, int K, float* sm) {
    int tid = threadIdx.x;
    int wid = tid >> 5, lane = tid & 31;
    int warpRow = wid >> 2, warpCol = wid & 3;
    int bm = blockIdx.y * 128, bn = blockIdx.x * 128;

    uint32_t s_base = (uint32_t)__cvta_generic_to_shared(sm);
    int ra = tid >> 3, ca = (tid & 7) * 4;
    int kb = tid >> 5, cb = (tid & 31) * 4;

    wmma::fragment<wmma::accumulator, 16, 16, 8, float> acc[4][2];
#pragma unroll
    for (int i = 0; i < 4; ++i)
#pragma unroll
        for (int j = 0; j < 2; ++j) wmma::fill_fragment(acc[i][j], 0.0f);

    const int KT = K >> 5;
    auto issue = [&](int stage, int k0) {
        uint32_t as = s_base + (uint32_t)(stage * 5120) * 4;
        uint32_t bs = s_base + (uint32_t)(10240 + stage * 5120) * 4;
#pragma unroll
        for (int it = 0; it < 4; ++it) {
            int r = ra + it * 32;
            cp16(as + (uint32_t)(r * 40 + ca) * 4, A + (size_t)(bm + r) * K + k0 + ca);
        }
        if (NT) {
#pragma unroll
            for (int it = 0; it < 4; ++it) {
                int r = ra + it * 32;
                cp16(bs + (uint32_t)(r * 40 + ca) * 4, B + (size_t)(bn + r) * K + k0 + ca);
            }
        } else {
#pragma unroll
            for (int it = 0; it < 4; ++it) {
                int kk = kb + it * 8;
                cp16(bs + (uint32_t)(kk * 136 + cb) * 4, B + (size_t)(k0 + kk) * N + bn + cb);
            }
        }
        CP_COMMIT();
    };

    issue(0, 0);
    for (int kt = 0; kt < KT; ++kt) {
        int stage = kt & 1;
        if (kt + 1 < KT) {
            issue(stage ^ 1, (kt + 1) * 32);
            CP_WAIT(1);
        } else {
            CP_WAIT(0);
        }
        __syncthreads();
        float* As = sm + stage * 5120;
        float* Bs = sm + 10240 + stage * 5120;
#pragma unroll
        for (int ks = 0; ks < 4; ++ks) {
            int kk = ks * 8;
            wmma::fragment<wmma::matrix_a, 16, 16, 8, wmma::precision::tf32, wmma::row_major> af[4];
#pragma unroll
            for (int i = 0; i < 4; ++i)
                wmma::load_matrix_sync(af[i], &As[(warpRow * 64 + i * 16) * 40 + kk], 40);
            if (NT) {
                wmma::fragment<wmma::matrix_b, 16, 16, 8, wmma::precision::tf32, wmma::col_major> bf[2];
#pragma unroll
                for (int j = 0; j < 2; ++j)
                    wmma::load_matrix_sync(bf[j], &Bs[(warpCol * 32 + j * 16) * 40 + kk], 40);
#pragma unroll
                for (int i = 0; i < 4; ++i)
#pragma unroll
                    for (int j = 0; j < 2; ++j) wmma::mma_sync(acc[i][j], af[i], bf[j], acc[i][j]);
            } else {
                wmma::fragment<wmma::matrix_b, 16, 16, 8, wmma::precision::tf32, wmma::row_major> bf[2];
#pragma unroll
                for (int j = 0; j < 2; ++j)
                    wmma::load_matrix_sync(bf[j], &Bs[kk * 136 + warpCol * 32 + j * 16], 136);
#pragma unroll
                for (int i = 0; i < 4; ++i)
#pragma unroll
                    for (int j = 0; j < 2; ++j) wmma::mma_sync(acc[i][j], af[i], bf[j], acc[i][j]);
            }
        }
        __syncthreads();
    }

    float* st = &sm[wid * 384];
#pragma unroll
    for (int i = 0; i < 4; ++i) {
#pragma unroll
        for (int j = 0; j < 2; ++j) {
            wmma::store_matrix_sync(st, acc[i][j], 24, wmma::mem_row_major);
            __syncwarp();
            int row0 = bm + warpRow * 64 + i * 16;
            int col0 = bn + warpCol * 32 + j * 16;
            int r = lane >> 1, c8 = (lane & 1) * 8;
            float4 v0 = *(float4*)&st[r * 24 + c8];
            float4 v1 = *(float4*)&st[r * 24 + c8 + 4];
            if (BIAS) {
                const float* bp = bias + col0 + c8;
                v0.x += bp[0]; v0.y += bp[1]; v0.z += bp[2]; v0.w += bp[3];
                v1.x += bp[4]; v1.y += bp[5]; v1.z += bp[6]; v1.w += bp[7];
            }
            if (EPI) {
                v0.x = gelu_exact(v0.x); v0.y = gelu_exact(v0.y);
                v0.z = gelu_exact(v0.z); v0.w = gelu_exact(v0.w);
                v1.x = gelu_exact(v1.x); v1.y = gelu_exact(v1.y);
                v1.z = gelu_exact(v1.z); v1.w = gelu_exact(v1.w);
            }
            if (RND) {
                v0.x = rtf(v0.x); v0.y = rtf(v0.y); v0.z = rtf(v0.z); v0.w = rtf(v0.w);
                v1.x = rtf(v1.x); v1.y = rtf(v1.y); v1.z = rtf(v1.z); v1.w = rtf(v1.w);
            }
            float* cp = C + (size_t)(row0 + r) * N + col0 + c8;
            *(float4*)cp = v0;
            *(float4*)(cp + 4) = v1;
            __syncwarp();
        }
    }
}

template <int NT, int EPI, int BIAS, int RND>
__global__ void __launch_bounds__(256, 2)
wmma_gemm(const float* __restrict__ A, const float* __restrict__ B,
          const float* __restrict__ bias, float* __restrict__ C, int M, int N, int K) {
    extern __shared__ float sm[];
    gemm_body<NT, EPI, BIAS, RND>(A, B, bias, C, M, N, K, sm);
}

__global__ void __launch_bounds__(256, 2)
wmma_gemm_fuse3(const float* A0, const float* B0, float* C0,
                const float* A1, const float* B1, float* C1,
                const float* A2, const float* B2, float* C2) {
    extern __shared__ float sm[];
    if (blockIdx.z == 0)
        gemm_body<0, 0, 0, 1>(A0, B0, nullptr, C0, 1024, 1024, 1024, sm);
    else if (blockIdx.z == 1)
        gemm_body<0, 0, 0, 1>(A1, B1, nullptr, C1, 1024, 1024, 1024, sm);
    else
        gemm_body<0, 0, 0, 1>(A2, B2, nullptr, C2, 1024, 1024, 1024, sm);
}

// ==================== TF32 WMMA GEMM 128x256 NT (kv projection) ====================
// Warp tile 64x64 (acc 4x4) -> fragment-load:MMA ratio 8:16. Dyn smem 120KB.
// A stage stride 5120 (ld 40); B stage stride 10240 (ld 40).
__global__ void __launch_bounds__(256, 1)
wmma_gemm_kv(const float* __restrict__ A, const float* __restrict__ B,
             const float* __restrict__ bias, float* __restrict__ C,
             int M, int N, int K) {
    extern __shared__ float sm[];
    int tid = threadIdx.x;
    int wid = tid >> 5, lane = tid & 31;
    int warpRow = wid >> 2, warpCol = wid & 3;   // 2 x 4 warps, 64x64 each
    int bm = blockIdx.y * 128, bn = blockIdx.x * 256;

    uint32_t s_base = (uint32_t)__cvta_generic_to_shared(sm);
    int ra = tid >> 3, ca = (tid & 7) * 4;

    wmma::fragment<wmma::accumulator, 16, 16, 8, float> acc[4][4];
#pragma unroll
    for (int i = 0; i < 4; ++i)
#pragma unroll
        for (int j = 0; j < 4; ++j) wmma::fill_fragment(acc[i][j], 0.0f);

    const int KT = K >> 5;
    auto issue = [&](int stage, int k0) {
        uint32_t as = s_base + (uint32_t)(stage * 5120) * 4;
        uint32_t bs = s_base + (uint32_t)(10240 + stage * 10240) * 4;
#pragma unroll
        for (int it = 0; it < 4; ++it) {
            int r = ra + it * 32;
            cp16(as + (uint32_t)(r * 40 + ca) * 4, A + (size_t)(bm + r) * K + k0 + ca);
        }
#pragma unroll
        for (int it = 0; it < 8; ++it) {
            int r = ra + it * 32;
            cp16(bs + (uint32_t)(r * 40 + ca) * 4, B + (size_t)(bn + r) * K + k0 + ca);
        }
        CP_COMMIT();
    };

    issue(0, 0);
    for (int kt = 0; kt < KT; ++kt) {
        int stage = kt & 1;
        if (kt + 1 < KT) {
            issue(stage ^ 1, (kt + 1) * 32);
            CP_WAIT(1);
        } else {
            CP_WAIT(0);
        }
        __syncthreads();
        float* As = sm + stage * 5120;
        float* Bs = sm + 10240 + stage * 10240;
#pragma unroll
        for (int ks = 0; ks < 4; ++ks) {
            int kk = ks * 8;
            wmma::fragment<wmma::matrix_a, 16, 16, 8, wmma::precision::tf32, wmma::row_major> af[4];
            wmma::fragment<wmma::matrix_b, 16, 16, 8, wmma::precision::tf32, wmma::col_major> bf[4];
#pragma unroll
            for (int i = 0; i < 4; ++i)
                wmma::load_matrix_sync(af[i], &As[(warpRow * 64 + i * 16) * 40 + kk], 40);
#pragma unroll
            for (int j = 0; j < 4; ++j)
                wmma::load_matrix_sync(bf[j], &Bs[(warpCol * 64 + j * 16) * 40 + kk], 40);
#pragma unroll
            for (int i = 0; i < 4; ++i)
#pragma unroll
                for (int j = 0; j < 4; ++j) wmma::mma_sync(acc[i][j], af[i], bf[j], acc[i][j]);
        }
        __syncthreads();
    }

    float* st = &sm[wid * 384];
#pragma unroll
    for (int i = 0; i < 4; ++i) {
#pragma unroll
        for (int j = 0; j < 4; ++j) {
            wmma::store_matrix_sync(st, acc[i][j], 24, wmma::mem_row_major);
            __syncwarp();
            int row0 = bm + warpRow * 64 + i * 16;
            int col0 = bn + warpCol * 64 + j * 16;
            int r = lane >> 1, c8 = (lane & 1) * 8;
            float4 v0 = *(float4*)&st[r * 24 + c8];
            float4 v1 = *(float4*)&st[r * 24 + c8 + 4];
            const float* bp = bias + col0 + c8;
            v0.x = rtf(v0.x + bp[0]); v0.y = rtf(v0.y + bp[1]);
            v0.z = rtf(v0.z + bp[2]); v0.w = rtf(v0.w + bp[3]);
            v1.x = rtf(v1.x + bp[4]); v1.y = rtf(v1.y + bp[5]);
            v1.z = rtf(v1.z + bp[6]); v1.w = rtf(v1.w + bp[7]);
            float* cp = C + (size_t)(row0 + r) * N + col0 + c8;
            *(float4*)cp = v0;
            *(float4*)(cp + 4) = v1;
            __syncwarp();
        }
    }
}

// ==================== scores (wmma): [64,128]-tile of Q K^T / 8, masked ==============
// grid (16, 128): x = s-chunk of 128, y = bh. Dyn smem 55296 B.
__global__ void __launch_bounds__(256)
scores_wmma(const float* __restrict__ qh, const float* __restrict__ kv,
            const int* __restrict__ cmask, float* __restrict__ probs) {
    extern __shared__ float sm[];
    float* Qs = sm;            // 64 x ld72
    float* Ks = sm + 4608;     // 128 x ld72
    int bh = blockIdx.y;
    int b = bh >> 4, h = bh & 15;
    int s0 = blockIdx.x * 128;
    int tid = threadIdx.x, wid = tid >> 5, lane = tid & 31;

#pragma unroll
    for (int it = 0; it < 4; ++it) {
        int v = tid + it * 256;
        int r = v >> 4, c = (v & 15) * 4;
        *(float4*)&Qs[r * 72 + c] = *(const float4*)(qh + (size_t)(b * 64 + r) * 1024 + h * 64 + c);
    }
#pragma unroll
    for (int it = 0; it < 8; ++it) {
        int v = tid + it * 256;
        int r = v >> 4, c = (v & 15) * 4;
        *(float4*)&Ks[r * 72 + c] =
            *(const float4*)(kv + (size_t)(b * 2048 + s0 + r) * 2048 + h * 64 + c);
    }
    __syncthreads();

    int warpRow = wid >> 2, warpCol = wid & 3;   // 2x4 warps: 32 rows x 32 cols
    wmma::fragment<wmma::accumulator, 16, 16, 8, float> acc[2][2];
#pragma unroll
    for (int i = 0; i < 2; ++i)
#pragma unroll
        for (int j = 0; j < 2; ++j) wmma::fill_fragment(acc[i][j], 0.0f);

#pragma unroll
    for (int ks = 0; ks < 8; ++ks) {
        int kk = ks * 8;
        wmma::fragment<wmma::matrix_a, 16, 16, 8, wmma::precision::tf32, wmma::row_major> af[2];
        wmma::fragment<wmma::matrix_b, 16, 16, 8, wmma::precision::tf32, wmma::col_major> bf[2];
#pragma unroll
        for (int i = 0; i < 2; ++i)
            wmma::load_matrix_sync(af[i], &Qs[(warpRow * 32 + i * 16) * 72 + kk], 72);
#pragma unroll
        for (int j = 0; j < 2; ++j)
            wmma::load_matrix_sync(bf[j], &Ks[(warpCol * 32 + j * 16) * 72 + kk], 72);
#pragma unroll
        for (int i = 0; i < 2; ++i)
#pragma unroll
            for (int j = 0; j < 2; ++j) wmma::mma_sync(acc[i][j], af[i], bf[j], acc[i][j]);
    }
    __syncthreads();

    const float NEG = __int_as_float(0xff800000);
    float* st = &sm[wid * 384];
#pragma unroll
    for (int i = 0; i < 2; ++i) {
#pragma unroll
        for (int j = 0; j < 2; ++j) {
            wmma::store_matrix_sync(st, acc[i][j], 24, wmma::mem_row_major);
            __syncwarp();
            int r = lane >> 1, c8 = (lane & 1) * 8;
            int l = warpRow * 32 + i * 16 + r;
            int sg = s0 + warpCol * 32 + j * 16 + c8;
            const int* mp = cmask + b * 2048 + sg;
            float4 v0 = *(float4*)&st[r * 24 + c8];
            float4 v1 = *(float4*)&st[r * 24 + c8 + 4];
            v0.x = mp[0] ? v0.x * 0.125f : NEG;
            v0.y = mp[1] ? v0.y * 0.125f : NEG;
            v0.z = mp[2] ? v0.z * 0.125f : NEG;
            v0.w = mp[3] ? v0.w * 0.125f : NEG;
            v1.x = mp[4] ? v1.x * 0.125f : NEG;
            v1.y = mp[5] ? v1.y * 0.125f : NEG;
            v1.z = mp[6] ? v1.z * 0.125f : NEG;
            v1.w = mp[7] ? v1.w * 0.125f : NEG;
            float* pp = probs + ((size_t)bh * 64 + l) * 2048 + sg;
            *(float4*)pp = v0;
            *(float4*)(pp + 4) = v1;
            __syncwarp();
        }
    }
}

// ---------------- row softmax over S=2048, in place; output tf32-rounded ----------
__global__ void softmax_kernel(float* __restrict__ probs) {
    size_t row = blockIdx.x;
    float4* p4 = (float4*)(probs + row * 2048);
    int tid = threadIdx.x;
    float4 x0 = p4[tid], x1 = p4[tid + 256];
    float mx = fmaxf(fmaxf(fmaxf(x0.x, x0.y), fmaxf(x0.z, x0.w)),
                     fmaxf(fmaxf(x1.x, x1.y), fmaxf(x1.z, x1.w)));
    __shared__ float red[256];
    red[tid] = mx;
    __syncthreads();
    for (int st = 128; st > 0; st >>= 1) {
        if (tid < st) red[tid] = fmaxf(red[tid], red[tid + st]);
        __syncthreads();
    }
    float m = red[0];
    __syncthreads();
    float e[8];
    e[0] = expf(x0.x - m); e[1] = expf(x0.y - m); e[2] = expf(x0.z - m); e[3] = expf(x0.w - m);
    e[4] = expf(x1.x - m); e[5] = expf(x1.y - m); e[6] = expf(x1.z - m); e[7] = expf(x1.w - m);
    float s = (e[0] + e[1]) + (e[2] + e[3]) + (e[4] + e[5]) + (e[6] + e[7]);
    red[tid] = s;
    __syncthreads();
    for (int st = 128; st > 0; st >>= 1) {
        if (tid < st) red[tid] += red[tid + st];
        __syncthreads();
    }
    float inv = 1.0f / red[0];
    float4 o0, o1;
    o0.x = rtf(e[0] * inv); o0.y = rtf(e[1] * inv); o0.z = rtf(e[2] * inv); o0.w = rtf(e[3] * inv);
    o1.x = rtf(e[4] * inv); o1.y = rtf(e[5] * inv); o1.z = rtf(e[6] * inv); o1.w = rtf(e[7] * inv);
    p4[tid] = o0;
    p4[tid + 256] = o1;
}

// ==================== attn (wmma): P @ V per (b,h), [64,2048]@[2048,64] ==============
// grid 128 = bh. Dyn smem 73728 B: Ps stages 2 x 4608, Vs stages 2 x 4608.
__global__ void __launch_bounds__(256)
attn_wmma(const float* __restrict__ probs, const float* __restrict__ kv,
          float* __restrict__ attn) {
    extern __shared__ float sm[];
    int bh = blockIdx.x;
    int b = bh >> 4, h = bh & 15;
    int tid = threadIdx.x, wid = tid >> 5, lane = tid & 31;
    int warpRow = wid >> 1, warpCol = wid & 1;   // 4x2 warps: 16 rows x 32 cols

    uint32_t s_base = (uint32_t)__cvta_generic_to_shared(sm);
    int ra = tid >> 4, ca = (tid & 15) * 4;      // 16 rows per 256-thread pass

    wmma::fragment<wmma::accumulator, 16, 16, 8, float> acc[2];
    wmma::fill_fragment(acc[0], 0.0f);
    wmma::fill_fragment(acc[1], 0.0f);

    auto issue = [&](int stage, int s0) {
        uint32_t ps = s_base + (uint32_t)(stage * 4608) * 4;
        uint32_t vs = s_base + (uint32_t)(9216 + stage * 4608) * 4;
#pragma unroll
        for (int it = 0; it < 4; ++it) {
            int r = ra + it * 16;
            cp16(ps + (uint32_t)(r * 72 + ca) * 4,
                 probs + ((size_t)bh * 64 + r) * 2048 + s0 + ca);
            cp16(vs + (uint32_t)(r * 72 + ca) * 4,
                 kv + (size_t)(b * 2048 + s0 + r) * 2048 + 1024 + h * 64 + ca);
        }
        CP_COMMIT();
    };

    issue(0, 0);
    for (int kt = 0; kt < 32; ++kt) {
        int stage = kt & 1;
        if (kt + 1 < 32) {
            issue(stage ^ 1, (kt + 1) * 64);
            CP_WAIT(1);
        } else {
            CP_WAIT(0);
        }
        __syncthreads();
        float* Ps = sm + stage * 4608;
        float* Vs = sm + 9216 + stage * 4608;
#pragma unroll
        for (int ks = 0; ks < 8; ++ks) {
            int kk = ks * 8;
            wmma::fragment<wmma::matrix_a, 16, 16, 8, wmma::precision::tf32, wmma::row_major> af;
            wmma::fragment<wmma::matrix_b, 16, 16, 8, wmma::precision::tf32, wmma::row_major> bf[2];
            wmma::load_matrix_sync(af, &Ps[(warpRow * 16) * 72 + kk], 72);
#pragma unroll
            for (int j = 0; j < 2; ++j)
                wmma::load_matrix_sync(bf[j], &Vs[kk * 72 + warpCol * 32 + j * 16], 72);
            wmma::mma_sync(acc[0], af, bf[0], acc[0]);
            wmma::mma_sync(acc[1], af, bf[1], acc[1]);
        }
        __syncthreads();
    }

    float* st = &sm[wid * 384];
#pragma unroll
    for (int j = 0; j < 2; ++j) {
        wmma::store_matrix_sync(st, acc[j], 24, wmma::mem_row_major);
        __syncwarp();
        int r = lane >> 1, c8 = (lane & 1) * 8;
        int l = warpRow * 16 + r;
        int d0 = warpCol * 32 + j * 16 + c8;
        float4 v0 = *(float4*)&st[r * 24 + c8];
        float4 v1 = *(float4*)&st[r * 24 + c8 + 4];
        v0.x = rtf(v0.x); v0.y = rtf(v0.y); v0.z = rtf(v0.z); v0.w = rtf(v0.w);
        v1.x = rtf(v1.x); v1.y = rtf(v1.y); v1.z = rtf(v1.z); v1.w = rtf(v1.w);
        float* ap = attn + (size_t)(b * 64 + l) * 1024 + h * 64 + d0;
        *(float4*)ap = v0;
        *(float4*)(ap + 4) = v1;
        __syncwarp();
    }
}

// ---------------- residual add + LayerNorm (optional rounded copy) ----------------
template <int WR>
__global__ void add_ln_kernel(const float* __restrict__ a, const float* __restrict__ b2,
                              const float* __restrict__ g, const float* __restrict__ bet,
                              float* __restrict__ out, float* __restrict__ out_r) {
    int row = blockIdx.x, tid = threadIdx.x;
    const float4* a4 = (const float4*)(a + (size_t)row * 1024);
    const float4* b4 = (const float4*)(b2 + (size_t)row * 1024);
    float4 va = a4[tid], vb = b4[tid];
    float4 x;
    x.x = va.x + vb.x; x.y = va.y + vb.y; x.z = va.z + vb.z; x.w = va.w + vb.w;
    float s = (x.x + x.y) + (x.z + x.w);
    float sq = x.x * x.x + x.y * x.y + x.z * x.z + x.w * x.w;
    __shared__ float r1[256], r2[256];
    r1[tid] = s; r2[tid] = sq;
    __syncthreads();
    for (int st = 128; st > 0; st >>= 1) {
        if (tid < st) { r1[tid] += r1[tid + st]; r2[tid] += r2[tid + st]; }
        __syncthreads();
    }
    float mean = r1[0] * (1.0f / 1024.0f);
    float var = r2[0] * (1.0f / 1024.0f) - mean * mean;
    float rstd = rsqrtf(var + 1e-5f);
    float4 gg = ((const float4*)g)[tid], bb = ((const float4*)bet)[tid];
    float4 o;
    o.x = (x.x - mean) * rstd * gg.x + bb.x;
    o.y = (x.y - mean) * rstd * gg.y + bb.y;
    o.z = (x.z - mean) * rstd * gg.z + bb.z;
    o.w = (x.w - mean) * rstd * gg.w + bb.w;
    ((float4*)(out + (size_t)row * 1024))[tid] = o;
    if (WR) {
        float4 q;
        q.x = rtf(o.x); q.y = rtf(o.y); q.z = rtf(o.z); q.w = rtf(o.w);
        ((float4*)(out_r + (size_t)row * 1024))[tid] = q;
    }
}

// ---------------- attn_weights = mean over heads of probs ----------------
__global__ void mean_heads_kernel(const float* __restrict__ probs, float* __restrict__ aw) {
    int i = blockIdx.x * 256 + threadIdx.x;
    int s4 = i & 511;
    int l = (i >> 9) & 63;
    int b = i >> 15;
    float4 acc = {0.f, 0.f, 0.f, 0.f};
#pragma unroll
    for (int h = 0; h < 16; ++h) {
        float4 p = *(const float4*)(probs + ((size_t)(b * 16 + h) * 64 + l) * 2048 + s4 * 4);
        acc.x += p.x; acc.y += p.y; acc.z += p.z; acc.w += p.w;
    }
    const float inv = 1.0f / 16.0f;
    acc.x *= inv; acc.y *= inv; acc.z *= inv; acc.w *= inv;
    *(float4*)(aw + ((size_t)(b * 64 + l) * 2048) + s4 * 4) = acc;
}

// ---------------- launch ----------------
extern "C" void kernel_launch(void* const* d_in, const int* in_sizes, int n_in,
                              void* d_out, int out_size) {
    (void)in_sizes; (void)n_in; (void)out_size;
    const float* latents = (const float*)d_in[0];
    const float* context = (const float*)d_in[1];
    const int* cmask = (const int*)d_in[2];
    const float* q_w = (const float*)d_in[3];
    const float* q_b = (const float*)d_in[4];
    const float* k_w = (const float*)d_in[5];
    const float* k_b = (const float*)d_in[6];
    const float* v_w = (const float*)d_in[7];
    const float* v_b = (const float*)d_in[8];
    const float* in_wq = (const float*)d_in[9];
    const float* in_bq = (const float*)d_in[10];
    const float* in_wk = (const float*)d_in[11];
    const float* in_bk = (const float*)d_in[12];
    const float* in_wv = (const float*)d_in[13];
    const float* in_bv = (const float*)d_in[14];
    const float* out_w = (const float*)d_in[15];
    const float* out_b = (const float*)d_in[16];
    const float* ln1_g = (const float*)d_in[17];
    const float* ln1_b = (const float*)d_in[18];
    const float* ln2_g = (const float*)d_in[19];
    const float* ln2_b = (const float*)d_in[20];
    const float* ff_w1 = (const float*)d_in[21];
    const float* ff_b1 = (const float*)d_in[22];
    const float* ff_w2 = (const float*)d_in[23];
    const float* ff_b2 = (const float*)d_in[24];

    float* out = (float*)d_out;
    float* aw_out = out + 512 * 1024;

    void* p;
    cudaGetSymbolAddress(&p, g_fuse6);  float* fuse6 = (float*)p;
    cudaGetSymbolAddress(&p, g_ctx_r);  float* ctx_r = (float*)p;
    cudaGetSymbolAddress(&p, g_lat_r);  float* lat_r = (float*)p;
    cudaGetSymbolAddress(&p, g_outw_r); float* outw_r = (float*)p;
    cudaGetSymbolAddress(&p, g_ffw1_r); float* ffw1_r = (float*)p;
    cudaGetSymbolAddress(&p, g_ffw2_r); float* ffw2_r = (float*)p;
    cudaGetSymbolAddress(&p, g_Wq);     float* Wq = (float*)p;
    cudaGetSymbolAddress(&p, g_Wkv);    float* Wkv = (float*)p;
    cudaGetSymbolAddress(&p, g_bq);     float* bq = (float*)p;
    cudaGetSymbolAddress(&p, g_bkv);    float* bkv = (float*)p;
    cudaGetSymbolAddress(&p, g_qh);     float* qh = (float*)p;
    cudaGetSymbolAddress(&p, g_kv);     float* kvb = (float*)p;
    cudaGetSymbolAddress(&p, g_probs);  float* probs = (float*)p;
    cudaGetSymbolAddress(&p, g_attn);   float* attn = (float*)p;
    cudaGetSymbolAddress(&p, g_x);      float* xb = (float*)p;
    cudaGetSymbolAddress(&p, g_xr);     float* xr = (float*)p;
    cudaGetSymbolAddress(&p, g_h1);     float* h1 = (float*)p;

    const int SMEM = 81920;
    cudaFuncSetAttribute(wmma_gemm_fuse3, cudaFuncAttributeMaxDynamicSharedMemorySize, SMEM);
    cudaFuncSetAttribute(wmma_gemm<1, 0, 1, 1>, cudaFuncAttributeMaxDynamicSharedMemorySize, SMEM);
    cudaFuncSetAttribute(wmma_gemm<1, 0, 1, 0>, cudaFuncAttributeMaxDynamicSharedMemorySize, SMEM);
    cudaFuncSetAttribute(wmma_gemm<1, 1, 1, 1>, cudaFuncAttributeMaxDynamicSharedMemorySize, SMEM);
    cudaFuncSetAttribute(wmma_gemm_kv, cudaFuncAttributeMaxDynamicSharedMemorySize, 122880);
    cudaFuncSetAttribute(scores_wmma, cudaFuncAttributeMaxDynamicSharedMemorySize, 55296);
    cudaFuncSetAttribute(attn_wmma, cudaFuncAttributeMaxDynamicSharedMemorySize, 73728);

    // ---- pre-round operands to tf32 (RNE) ----
    round6_kernel<<<dim3(1024, 6), 256>>>((const float4*)in_wq, (const float4*)q_w,
                                          (const float4*)in_wk, (const float4*)k_w,
                                          (const float4*)in_wv, (const float4*)v_w,
                                          (float4*)fuse6);
    round_tf32_kernel<<<16384, 256>>>((const float4*)context, (float4*)ctx_r, 4194304);
    round_tf32_kernel<<<512, 256>>>((const float4*)latents, (float4*)lat_r, 131072);
    round_tf32_kernel<<<1024, 256>>>((const float4*)out_w, (float4*)outw_r, 262144);
    round_tf32_kernel<<<4096, 256>>>((const float4*)ff_w1, (float4*)ffw1_r, 1048576);
    round_tf32_kernel<<<4096, 256>>>((const float4*)ff_w2, (float4*)ffw2_r, 1048576);

    // ---- fused weights/biases, batched ----
    fuse_bias_kernel<<<1024, 256>>>(in_wq, q_b, in_bq, bq);
    fuse_bias_kernel<<<1024, 256>>>(in_wk, k_b, in_bk, bkv);
    fuse_bias_kernel<<<1024, 256>>>(in_wv, v_b, in_bv, bkv + 1024);
    const size_t MM = 1024 * 1024;
    wmma_gemm_fuse3<<<dim3(8, 8, 3), 256, SMEM>>>(
        fuse6 + 0 * MM, fuse6 + 1 * MM, Wq,
        fuse6 + 2 * MM, fuse6 + 3 * MM, Wkv,
        fuse6 + 4 * MM, fuse6 + 5 * MM, Wkv + 1024 * 1024);

    // ---- projections ----
    wmma_gemm<1, 0, 1, 1><<<dim3(8, 4), 256, SMEM>>>(lat_r, Wq, bq, qh, 512, 1024, 1024);
    wmma_gemm_kv<<<dim3(8, 128), 256, 122880>>>(ctx_r, Wkv, bkv, kvb, 16384, 2048, 1024);

    // ---- attention (tensor cores) ----
    scores_wmma<<<dim3(16, 128), 256, 55296>>>(qh, kvb, cmask, probs);
    softmax_kernel<<<8192, 256>>>(probs);
    attn_wmma<<<128, 256, 73728>>>(probs, kvb, attn);

    // ---- out projection (reuse qh for attn_out) ----
    wmma_gemm<1, 0, 1, 0><<<dim3(8, 4), 256, SMEM>>>(attn, outw_r, out_b, qh, 512, 1024, 1024);

    // ---- LN1 (exact + rounded copy) ----
    add_ln_kernel<1><<<512, 256>>>(latents, qh, ln1_g, ln1_b, xb, xr);

    // ---- FFN ----
    wmma_gemm<1, 1, 1, 1><<<dim3(32, 4), 256, SMEM>>>(xr, ffw1_r, ff_b1, h1, 512, 4096, 1024);
    wmma_gemm<1, 0, 1, 0><<<dim3(8, 4), 256, SMEM>>>(h1, ffw2_r, ff_b2, attn, 512, 1024, 4096);

    // ---- LN2 -> out ----
    add_ln_kernel<0><<<512, 256>>>(xb, attn, ln2_g, ln2_b, out, nullptr);

    // ---- attn_weights -> second output region ----
    mean_heads_kernel<<<1024, 256>>>(probs, aw_out);
}